// round 1
// baseline (speedup 1.0000x reference)
#include <cuda_runtime.h>
#include <math.h>

#define NSAMP 8192
#define MODES 32
#define KDIM  64          // 32 cos + 32 sin columns
#define BATCH 32
#define CH    64
#define ROWS  2048        // BATCH*CH
#define LSEG  20
#define MCHEB 8
#define NNODES 160        // LSEG*MCHEB

static __device__ __constant__ double D_PI = 3.14159265358979323846;

// ---------------- device scratch (no allocations allowed) ----------------
__device__ float g_Ftab [NSAMP*KDIM];   // [n][k]  k<32: cos(2pi k n/N), k>=32: sin(2pi (k-32) n/N)
__device__ float g_FtabT[KDIM*NSAMP];   // [k][n]
__device__ float g_Ar[NNODES*MODES];
__device__ float g_Ai[NNODES*MODES];
__device__ int   g_nodeL[NNODES];
__device__ float g_nodeWL[NNODES];
__device__ float g_nodeWR[NNODES];
__device__ float g_sfor[ROWS*KDIM];     // forward sums: [row][k]  (xr = s[f], xi = -s[32+f])
__device__ float g_mag [ROWS*MODES];
__device__ float g_gate[BATCH*CH*MODES];
__device__ float g_coef[ROWS*KDIM];     // inverse coefficients
__device__ float g_w1Tr[MODES*CH*CH];   // [f][i][o]
__device__ float g_w1Ti[MODES*CH*CH];

// ---------------- setup: DFT twiddle tables ----------------
__global__ void k_setup_F() {
    int idx = blockIdx.x * blockDim.x + threadIdx.x;
    if (idx >= NSAMP * KDIM) return;
    int n = idx / KDIM, k = idx % KDIM;
    int kf = (k < MODES) ? k : (k - MODES);
    long m = ((long)n * (long)kf) & (NSAMP - 1);         // exact phase reduction
    double ph = (double)m * (2.0 * D_PI / (double)NSAMP);
    float v = (k < MODES) ? (float)cos(ph) : (float)sin(ph);
    g_Ftab[n * KDIM + k]  = v;
    g_FtabT[k * NSAMP + n] = v;
}

// ---------------- setup: CFT quadrature tables (faithful to reference) -----
__global__ void k_setup_cft() {
    int tid = threadIdx.x;
    if (tid < NNODES) {
        int l = tid / MCHEB, m = tid % MCHEB;
        double cheb = -cos((2.0 * m + 1.0) * D_PI / (2.0 * MCHEB));
        double tseg = (double)l / LSEG + (1.0 / (2.0 * LSEG)) * (cheb + 1.0);
        // searchsorted(t, tseg) over t[i] = i/(N-1): smallest i with i/(N-1) >= tseg
        int right = (int)ceil(tseg * (double)(NSAMP - 1));
        if (right < 1) right = 1;
        if (right > NSAMP - 1) right = NSAMP - 1;
        int left = right - 1;
        double wr = (tseg * (double)(NSAMP - 1) - (double)left) / (double)(right - left);
        g_nodeL[tid]  = left;
        g_nodeWR[tid] = (float)wr;
        g_nodeWL[tid] = (float)(1.0 - wr);
    }
    for (int idx = tid; idx < NNODES * MODES; idx += blockDim.x) {
        int j = idx / MODES, f = idx % MODES;
        int l = j / MCHEB, m = j % MCHEB;   // m plays the Chebyshev-order role (as in reference einsum)
        double Wr = 0.0, Wi = 0.0;
        for (int mp = 0; mp < MCHEB; mp++) {
            double chebp = -cos((2.0 * mp + 1.0) * D_PI / (2.0 * MCHEB));
            double Tkm = cos((double)m * acos(chebp));
            double ang = chebp * (double)f * (D_PI / (double)LSEG); // f * 2pi*seg_len/2
            Wr += Tkm * cos(ang);
            Wi += Tkm * (-sin(ang));
        }
        double s = 1.0 / (2.0 * LSEG);
        Wr *= s; Wi *= s;
        double phi = 2.0 * D_PI * ((double)l / LSEG) * (double)f;
        double cphi = cos(phi), sphi = sin(phi);
        g_Ar[idx] = (float)( Wr * cphi + Wi * sphi);
        g_Ai[idx] = (float)(-Wr * sphi + Wi * cphi);
    }
}

// ---------------- setup: transpose w1 to f-major ----------------
__global__ void k_transpose_w1(const float* __restrict__ wr, const float* __restrict__ wi) {
    int idx = blockIdx.x * blockDim.x + threadIdx.x;
    if (idx >= MODES * CH * CH) return;
    int f = idx / (CH * CH);
    int rem = idx % (CH * CH);
    int i = rem / CH, o = rem % CH;
    g_w1Tr[idx] = wr[(i * CH + o) * MODES + f];
    g_w1Ti[idx] = wi[(i * CH + o) * MODES + f];
}

__global__ void k_zero_sfor() {
    int idx = blockIdx.x * blockDim.x + threadIdx.x;
    if (idx < ROWS * KDIM) g_sfor[idx] = 0.0f;
}

// ---------------- forward: S[2048x64] = X[2048x8192] * Ftab[8192x64] ------
// BM=64, BN=64, BK=16, 256 thr (16x16), TM=TN=4, K-split=8 with atomics.
__global__ __launch_bounds__(256) void k_forward(const float* __restrict__ x) {
    __shared__ float sX[16][64];   // [kk][m]
    __shared__ float sF[16][64];   // [kk][c]
    const int m0 = blockIdx.x * 64;
    const int kbase = blockIdx.y * (NSAMP / 8);
    const int tid = threadIdx.x;
    const int tx = tid & 15, ty = tid >> 4;
    const int lm = tid >> 2;            // row in X tile (0..63)
    const int lk = (tid & 3) * 4;       // k quad (0,4,8,12)
    const int fk = tid >> 4;            // row in F tile (0..15)
    const int fc = (tid & 15) * 4;      // col quad

    float acc[4][4];
#pragma unroll
    for (int i = 0; i < 4; i++)
#pragma unroll
        for (int j = 0; j < 4; j++) acc[i][j] = 0.0f;

    for (int kt = 0; kt < NSAMP / 8; kt += 16) {
        const int k0 = kbase + kt;
        float4 vx = *(const float4*)&x[(size_t)(m0 + lm) * NSAMP + k0 + lk];
        sX[lk + 0][lm] = vx.x; sX[lk + 1][lm] = vx.y;
        sX[lk + 2][lm] = vx.z; sX[lk + 3][lm] = vx.w;
        float4 vf = *(const float4*)&g_Ftab[(size_t)(k0 + fk) * KDIM + fc];
        *(float4*)&sF[fk][fc] = vf;
        __syncthreads();
#pragma unroll
        for (int kk = 0; kk < 16; kk++) {
            float4 a4 = *(float4*)&sX[kk][ty * 4];
            float4 b4 = *(float4*)&sF[kk][tx * 4];
            float av[4] = {a4.x, a4.y, a4.z, a4.w};
            float bv[4] = {b4.x, b4.y, b4.z, b4.w};
#pragma unroll
            for (int i = 0; i < 4; i++)
#pragma unroll
                for (int j = 0; j < 4; j++)
                    acc[i][j] = fmaf(av[i], bv[j], acc[i][j]);
        }
        __syncthreads();
    }
#pragma unroll
    for (int i = 0; i < 4; i++)
#pragma unroll
        for (int j = 0; j < 4; j++)
            atomicAdd(&g_sfor[(size_t)(m0 + ty * 4 + i) * KDIM + tx * 4 + j], acc[i][j]);
}

// ---------------- CFT magnitude ----------------
__global__ void k_mag(const float* __restrict__ x) {
    __shared__ float v[NNODES];
    const int row = blockIdx.x;
    const int tid = threadIdx.x;
    if (tid < NNODES) {
        int l = g_nodeL[tid];
        v[tid] = g_nodeWL[tid] * x[(size_t)row * NSAMP + l]
               + g_nodeWR[tid] * x[(size_t)row * NSAMP + l + 1];
    }
    __syncthreads();
    if (tid < MODES) {
        float re = 0.0f, im = 0.0f;
#pragma unroll 4
        for (int j = 0; j < NNODES; j++) {
            float vv = v[j];
            re = fmaf(vv, g_Ar[j * MODES + tid], re);
            im = fmaf(vv, g_Ai[j * MODES + tid], im);
        }
        g_mag[(size_t)row * MODES + tid] = sqrtf(re * re + im * im);
    }
}

// ---------------- LayerNorm + 1x1 conv gate (one block per batch b) -------
__global__ void k_ln_gate(const float* __restrict__ gate_w,
                          const float* __restrict__ gamma,
                          const float* __restrict__ beta) {
    __shared__ float sm[CH * MODES];
    __shared__ float sg[CH * MODES];
    const int b = blockIdx.x;
    const int tid = threadIdx.x;
    for (int e = tid; e < CH * MODES; e += blockDim.x)
        sm[e] = g_mag[(size_t)b * CH * MODES + e];
    __syncthreads();
    if (tid < CH) {
        float mu = 0.0f;
        for (int f = 0; f < MODES; f++) mu += sm[tid * MODES + f];
        mu *= (1.0f / MODES);
        float var = 0.0f;
        for (int f = 0; f < MODES; f++) {
            float d = sm[tid * MODES + f] - mu;
            var = fmaf(d, d, var);
        }
        var *= (1.0f / MODES);
        float inv = rsqrtf(var + 1e-5f);
        for (int f = 0; f < MODES; f++)
            sg[tid * MODES + f] = (sm[tid * MODES + f] - mu) * inv * gamma[f] + beta[f];
    }
    __syncthreads();
    for (int e = tid; e < CH * MODES; e += blockDim.x) {
        int o = e / MODES, f = e % MODES;
        float z = 0.0f;
#pragma unroll 4
        for (int i = 0; i < CH; i++)
            z = fmaf(gate_w[o * CH + i], sg[i * MODES + f], z);
        g_gate[(size_t)b * CH * MODES + e] = 1.0f / (1.0f + expf(-z));
    }
}

// -------- per-(b,f) 64x64 complex matvec + irfft coefficient prep ---------
__global__ void k_modes() {
    const int b = blockIdx.x, f = blockIdx.y;
    const int o = threadIdx.x;
    __shared__ float gr[CH], gi[CH];
    {
        int i = o;
        float g = g_gate[((size_t)b * CH + i) * MODES + f];
        gr[i] =  g_sfor[((size_t)b * CH + i) * KDIM + f] * g;          // xr * gate
        gi[i] = -g_sfor[((size_t)b * CH + i) * KDIM + MODES + f] * g;  // xi * gate
    }
    __syncthreads();
    float orr = 0.0f, oii = 0.0f;
    const float* wr = &g_w1Tr[(size_t)f * CH * CH];
    const float* wi = &g_w1Ti[(size_t)f * CH * CH];
#pragma unroll 4
    for (int i = 0; i < CH; i++) {
        float a = gr[i], c = gi[i];
        float xr = wr[i * CH + o], xi = wi[i * CH + o];
        orr = fmaf(a, xr, orr); orr = fmaf(-c, xi, orr);
        oii = fmaf(a, xi, oii); oii = fmaf( c, xr, oii);
    }
    // irfft of 32-mode-truncated spectrum; imag of bin 0 ignored by hc2r
    float sc = (f == 0) ? (1.0f / NSAMP) : (2.0f / NSAMP);
    int row = b * CH + o;
    g_coef[(size_t)row * KDIM + f] = sc * orr;
    g_coef[(size_t)row * KDIM + MODES + f] = (f == 0) ? 0.0f : (-sc * oii);
}

// ---------------- inverse: out = coef[2048x64] * FtabT[64x8192] -----------
// block: 16 rows x 1024 cols; 256 threads, 4 cols (float4) x 16 rows each.
__global__ __launch_bounds__(256) void k_inverse(float* __restrict__ out) {
    __shared__ float sct[KDIM][16];   // [k][r]
    const int n0 = blockIdx.x * 1024;
    const int r0 = blockIdx.y * 16;
    const int tid = threadIdx.x;
    {
        int e = tid * 4;
        int r = e / KDIM, c0 = e % KDIM;
        float4 v = *(const float4*)&g_coef[(size_t)(r0 + r) * KDIM + c0];
        sct[c0 + 0][r] = v.x; sct[c0 + 1][r] = v.y;
        sct[c0 + 2][r] = v.z; sct[c0 + 3][r] = v.w;
    }
    __syncthreads();
    const int n = n0 + tid * 4;
    float4 acc[16];
#pragma unroll
    for (int r = 0; r < 16; r++) acc[r] = make_float4(0.f, 0.f, 0.f, 0.f);

#pragma unroll 4
    for (int k = 0; k < KDIM; k++) {
        float4 fv = *(const float4*)&g_FtabT[(size_t)k * NSAMP + n];
        float4 c0 = *(float4*)&sct[k][0];
        float4 c1 = *(float4*)&sct[k][4];
        float4 c2 = *(float4*)&sct[k][8];
        float4 c3 = *(float4*)&sct[k][12];
        float cf[16] = {c0.x, c0.y, c0.z, c0.w, c1.x, c1.y, c1.z, c1.w,
                        c2.x, c2.y, c2.z, c2.w, c3.x, c3.y, c3.z, c3.w};
#pragma unroll
        for (int r = 0; r < 16; r++) {
            acc[r].x = fmaf(fv.x, cf[r], acc[r].x);
            acc[r].y = fmaf(fv.y, cf[r], acc[r].y);
            acc[r].z = fmaf(fv.z, cf[r], acc[r].z);
            acc[r].w = fmaf(fv.w, cf[r], acc[r].w);
        }
    }
#pragma unroll
    for (int r = 0; r < 16; r++)
        *(float4*)&out[(size_t)(r0 + r) * NSAMP + n] = acc[r];
}

// ---------------- launch ----------------
extern "C" void kernel_launch(void* const* d_in, const int* in_sizes, int n_in,
                              void* d_out, int out_size) {
    const float* x     = (const float*)d_in[0];
    const float* w1r   = (const float*)d_in[1];
    const float* w1i   = (const float*)d_in[2];
    const float* gw    = (const float*)d_in[3];
    const float* gamma = (const float*)d_in[4];
    const float* beta  = (const float*)d_in[5];
    float* out = (float*)d_out;

    k_setup_F<<<(NSAMP * KDIM + 255) / 256, 256>>>();
    k_setup_cft<<<1, 256>>>();
    k_transpose_w1<<<(MODES * CH * CH + 255) / 256, 256>>>(w1r, w1i);
    k_zero_sfor<<<(ROWS * KDIM + 255) / 256, 256>>>();
    k_forward<<<dim3(ROWS / 64, 8), 256>>>(x);
    k_mag<<<ROWS, NNODES>>>(x);
    k_ln_gate<<<BATCH, 256>>>(gw, gamma, beta);
    k_modes<<<dim3(BATCH, MODES), CH>>>();
    k_inverse<<<dim3(NSAMP / 1024, ROWS / 16), 256>>>(out);
}

// round 4
// speedup vs baseline: 5.1608x; 5.1608x over previous
#include <cuda_runtime.h>
#include <math.h>

#define NSAMP 8192
#define MODES 32
#define KDIM  64          // 32 cos + 32 sin columns
#define BATCH 32
#define CH    64
#define ROWS  2048        // BATCH*CH
#define LSEG  20
#define MCHEB 8
#define NNODES 160        // LSEG*MCHEB
#define KSPLIT 16

static __device__ __constant__ double D_PI = 3.14159265358979323846;

// packed f32x2 FMA (sm_103a FFMA2; PTX-only path)
#define FMA2(d, a, b, c) \
    asm("fma.rn.f32x2 %0, %1, %2, %3;" : "=l"(d) : "l"(a), "l"(b), "l"(c))

// ---------------- device scratch (no allocations allowed) ----------------
__device__ float  g_Ftab [NSAMP*KDIM];   // [n][k]  k<32: cos(2pi k n/N), k>=32: sin
__device__ float  g_FtabT[KDIM*NSAMP];   // [k][n]
__device__ double g_Wr[MCHEB*MODES];     // quadrature weights (segment-independent)
__device__ double g_Wi[MCHEB*MODES];
__device__ float  g_Ar[NNODES*MODES];
__device__ float  g_Ai[NNODES*MODES];
__device__ int    g_nodeL[NNODES];
__device__ float  g_nodeWL[NNODES];
__device__ float  g_nodeWR[NNODES];
__device__ float  g_sfor[ROWS*KDIM];     // forward sums: xr = s[f], xi = -s[32+f]
__device__ float  g_mag [ROWS*MODES];
__device__ float  g_gate[BATCH*CH*MODES];
__device__ float  g_coef[ROWS*KDIM];     // inverse coefficients
__device__ float  g_w1Tr[MODES*CH*CH];   // [f][i][o]
__device__ float  g_w1Ti[MODES*CH*CH];

// ---------------- setup: DFT twiddle tables (float, exact reduction) ------
__global__ void k_setup_F() {
    int idx = blockIdx.x * blockDim.x + threadIdx.x;
    if (idx < ROWS * KDIM) g_sfor[idx] = 0.0f;           // fold in the zeroing
    if (idx >= NSAMP * KDIM) return;
    int n = idx >> 6, k = idx & 63;
    int kf = k & 31;
    int m = (n * kf) & (NSAMP - 1);                      // exact phase mod 2pi
    float xm = (float)m * (1.0f / 4096.0f);              // exact (pow2 denom)
    float v = (k < MODES) ? cospif(xm) : sinpif(xm);
    g_Ftab[idx] = v;
    g_FtabT[k * NSAMP + n] = v;
}

// ---------------- setup: quadrature weights W[k][f] + interp nodes --------
__global__ void k_setup_W() {
    int tid = threadIdx.x;                                // 256 threads
    {
        int kc = tid >> 5, f = tid & 31;                  // Chebyshev order, freq
        double Wr = 0.0, Wi = 0.0;
        for (int mp = 0; mp < MCHEB; mp++) {
            double chebp = -cos((2.0 * mp + 1.0) * D_PI / (2.0 * MCHEB));
            double Tkm = cos((double)kc * acos(chebp));
            double ang = chebp * (double)f * (D_PI / (double)LSEG);
            Wr += Tkm * cos(ang);
            Wi += Tkm * (-sin(ang));
        }
        double s = 1.0 / (2.0 * LSEG);
        g_Wr[tid] = Wr * s;
        g_Wi[tid] = Wi * s;
    }
    if (tid < NNODES) {
        int l = tid / MCHEB, m = tid % MCHEB;
        double cheb = -cos((2.0 * m + 1.0) * D_PI / (2.0 * MCHEB));
        double tseg = (double)l / LSEG + (1.0 / (2.0 * LSEG)) * (cheb + 1.0);
        int right = (int)ceil(tseg * (double)(NSAMP - 1)); // searchsorted over i/(N-1)
        if (right < 1) right = 1;
        if (right > NSAMP - 1) right = NSAMP - 1;
        int left = right - 1;
        double wr = tseg * (double)(NSAMP - 1) - (double)left;
        g_nodeL[tid]  = left;
        g_nodeWR[tid] = (float)wr;
        g_nodeWL[tid] = (float)(1.0 - wr);
    }
}

// ---------------- setup: combined CFT matrices Ar/Ai [l][m][f] ------------
__global__ void k_setup_A() {
    int idx = blockIdx.x * blockDim.x + threadIdx.x;      // 5120 entries
    if (idx >= NNODES * MODES) return;
    int j = idx >> 5, f = idx & 31;
    int l = j >> 3, mc = j & 7;       // mc = Chebyshev-order index (as in reference einsum)
    double Wr = g_Wr[mc * MODES + f], Wi = g_Wi[mc * MODES + f];
    int r = (l * f) % LSEG;                               // exact reduction of l*f/20
    double phi = 2.0 * D_PI * ((double)r / (double)LSEG);
    double cphi = cos(phi), sphi = sin(phi);
    g_Ar[idx] = (float)( Wr * cphi + Wi * sphi);
    g_Ai[idx] = (float)(-Wr * sphi + Wi * cphi);
}

// ---------------- setup: transpose w1 to f-major ----------------
__global__ void k_transpose_w1(const float* __restrict__ wr, const float* __restrict__ wi) {
    int idx = blockIdx.x * blockDim.x + threadIdx.x;
    if (idx >= MODES * CH * CH) return;
    int f = idx / (CH * CH);
    int rem = idx % (CH * CH);
    int i = rem / CH, o = rem % CH;
    g_w1Tr[idx] = wr[(i * CH + o) * MODES + f];
    g_w1Ti[idx] = wi[(i * CH + o) * MODES + f];
}

// ---------------- forward: S[2048x64] = X[2048x8192] * Ftab[8192x64] ------
// BM=64, BN=64, BK=16, 256 thr, TM=4, TN=4 (as 2 f32x2 pairs), K-split=16.
__global__ __launch_bounds__(256) void k_forward(const float* __restrict__ x) {
    __shared__ float2 sXd[16][64];   // duplicated (v,v) for packed broadcast
    __shared__ float  sF[16][64];
    const int m0 = blockIdx.x * 64;
    const int kbase = blockIdx.y * (NSAMP / KSPLIT);
    const int tid = threadIdx.x;
    const int tx = tid & 15, ty = tid >> 4;
    const int lm = tid >> 2;            // row in X tile (0..63)
    const int lk = (tid & 3) * 4;       // k quad
    const int fk = tid >> 4;            // row in F tile
    const int fc = (tid & 15) * 4;      // col quad

    unsigned long long acc[4][2];
#pragma unroll
    for (int i = 0; i < 4; i++) { acc[i][0] = 0ull; acc[i][1] = 0ull; }

    for (int kt = 0; kt < NSAMP / KSPLIT; kt += 16) {
        const int k0 = kbase + kt;
        float4 vx = *(const float4*)&x[(size_t)(m0 + lm) * NSAMP + k0 + lk];
        sXd[lk + 0][lm] = make_float2(vx.x, vx.x);
        sXd[lk + 1][lm] = make_float2(vx.y, vx.y);
        sXd[lk + 2][lm] = make_float2(vx.z, vx.z);
        sXd[lk + 3][lm] = make_float2(vx.w, vx.w);
        float4 vf = *(const float4*)&g_Ftab[(size_t)(k0 + fk) * KDIM + fc];
        *(float4*)&sF[fk][fc] = vf;
        __syncthreads();
#pragma unroll
        for (int kk = 0; kk < 16; kk++) {
            const unsigned long long* bp =
                (const unsigned long long*)&sF[kk][tx * 4];
            unsigned long long b0 = bp[0], b1 = bp[1];
#pragma unroll
            for (int i = 0; i < 4; i++) {
                unsigned long long a =
                    *(const unsigned long long*)&sXd[kk][ty * 4 + i];
                FMA2(acc[i][0], a, b0, acc[i][0]);
                FMA2(acc[i][1], a, b1, acc[i][1]);
            }
        }
        __syncthreads();
    }
#pragma unroll
    for (int i = 0; i < 4; i++) {
#pragma unroll
        for (int jp = 0; jp < 2; jp++) {
            float2 v = *(float2*)&acc[i][jp];
            float* dst = &g_sfor[(size_t)(m0 + ty * 4 + i) * KDIM + tx * 4 + jp * 2];
            atomicAdd(dst + 0, v.x);
            atomicAdd(dst + 1, v.y);
        }
    }
}

// ---------------- CFT magnitude ----------------
__global__ void k_mag(const float* __restrict__ x) {
    __shared__ float v[NNODES];
    const int row = blockIdx.x;
    const int tid = threadIdx.x;
    if (tid < NNODES) {
        int l = g_nodeL[tid];
        v[tid] = g_nodeWL[tid] * x[(size_t)row * NSAMP + l]
               + g_nodeWR[tid] * x[(size_t)row * NSAMP + l + 1];
    }
    __syncthreads();
    if (tid < MODES) {
        float re = 0.0f, im = 0.0f;
#pragma unroll 8
        for (int j = 0; j < NNODES; j++) {
            float vv = v[j];
            re = fmaf(vv, __ldg(&g_Ar[j * MODES + tid]), re);
            im = fmaf(vv, __ldg(&g_Ai[j * MODES + tid]), im);
        }
        g_mag[(size_t)row * MODES + tid] = sqrtf(re * re + im * im);
    }
}

// ---------------- LayerNorm + 1x1 conv gate (one block per batch b) -------
__global__ void k_ln_gate(const float* __restrict__ gate_w,
                          const float* __restrict__ gamma,
                          const float* __restrict__ beta) {
    __shared__ float sm[CH * MODES];
    __shared__ float sg[CH * MODES];
    const int b = blockIdx.x;
    const int tid = threadIdx.x;
    for (int e = tid; e < CH * MODES; e += blockDim.x)
        sm[e] = g_mag[(size_t)b * CH * MODES + e];
    __syncthreads();
    if (tid < CH) {
        float mu = 0.0f;
        for (int f = 0; f < MODES; f++) mu += sm[tid * MODES + f];
        mu *= (1.0f / MODES);
        float var = 0.0f;
        for (int f = 0; f < MODES; f++) {
            float d = sm[tid * MODES + f] - mu;
            var = fmaf(d, d, var);
        }
        var *= (1.0f / MODES);
        float inv = rsqrtf(var + 1e-5f);
        for (int f = 0; f < MODES; f++)
            sg[tid * MODES + f] = (sm[tid * MODES + f] - mu) * inv * gamma[f] + beta[f];
    }
    __syncthreads();
    for (int e = tid; e < CH * MODES; e += blockDim.x) {
        int o = e / MODES, f = e % MODES;
        float z = 0.0f;
#pragma unroll 8
        for (int i = 0; i < CH; i++)
            z = fmaf(gate_w[o * CH + i], sg[i * MODES + f], z);
        g_gate[(size_t)b * CH * MODES + e] = 1.0f / (1.0f + expf(-z));
    }
}

// -------- per-(b,f) 64x64 complex matvec + irfft coefficient prep ---------
__global__ void k_modes() {
    const int b = blockIdx.x, f = blockIdx.y;
    const int o = threadIdx.x;
    __shared__ float gr[CH], gi[CH];
    {
        int i = o;
        float g = g_gate[((size_t)b * CH + i) * MODES + f];
        gr[i] =  g_sfor[((size_t)b * CH + i) * KDIM + f] * g;          // xr * gate
        gi[i] = -g_sfor[((size_t)b * CH + i) * KDIM + MODES + f] * g;  // xi * gate
    }
    __syncthreads();
    float orr = 0.0f, oii = 0.0f;
    const float* wr = &g_w1Tr[(size_t)f * CH * CH];
    const float* wi = &g_w1Ti[(size_t)f * CH * CH];
#pragma unroll 8
    for (int i = 0; i < CH; i++) {
        float a = gr[i], c = gi[i];
        float xr = wr[i * CH + o], xi = wi[i * CH + o];
        orr = fmaf(a, xr, orr); orr = fmaf(-c, xi, orr);
        oii = fmaf(a, xi, oii); oii = fmaf( c, xr, oii);
    }
    // irfft of 32-mode-truncated spectrum; imag of bin 0 ignored by hc2r
    float sc = (f == 0) ? (1.0f / NSAMP) : (2.0f / NSAMP);
    int row = b * CH + o;
    g_coef[(size_t)row * KDIM + f] = sc * orr;
    g_coef[(size_t)row * KDIM + MODES + f] = (f == 0) ? 0.0f : (-sc * oii);
}

// ---------------- inverse: out = coef[2048x64] * FtabT[64x8192] -----------
// block: 16 rows x 1024 cols; 256 threads; packed f32x2 accumulation.
__global__ __launch_bounds__(256) void k_inverse(float* __restrict__ out) {
    __shared__ float2 sctd[KDIM][16];   // duplicated (v,v) per [k][r]
    const int n0 = blockIdx.x * 1024;
    const int r0 = blockIdx.y * 16;
    const int tid = threadIdx.x;
    {
        int e = tid * 4;
        int r = e >> 6, c0 = e & 63;
        float4 v = *(const float4*)&g_coef[(size_t)(r0 + r) * KDIM + c0];
        sctd[c0 + 0][r] = make_float2(v.x, v.x);
        sctd[c0 + 1][r] = make_float2(v.y, v.y);
        sctd[c0 + 2][r] = make_float2(v.z, v.z);
        sctd[c0 + 3][r] = make_float2(v.w, v.w);
    }
    __syncthreads();
    const int n = n0 + tid * 4;
    unsigned long long acc0[16], acc1[16];
#pragma unroll
    for (int r = 0; r < 16; r++) { acc0[r] = 0ull; acc1[r] = 0ull; }

#pragma unroll 2
    for (int k = 0; k < KDIM; k++) {
        float4 fv = *(const float4*)&g_FtabT[(size_t)k * NSAMP + n];
        unsigned long long f01 = *(unsigned long long*)&fv.x;
        unsigned long long f23 = *(unsigned long long*)&fv.z;
#pragma unroll
        for (int r = 0; r < 16; r++) {
            unsigned long long c = *(const unsigned long long*)&sctd[k][r];
            FMA2(acc0[r], f01, c, acc0[r]);
            FMA2(acc1[r], f23, c, acc1[r]);
        }
    }
#pragma unroll
    for (int r = 0; r < 16; r++) {
        float2 lo = *(float2*)&acc0[r];
        float2 hi = *(float2*)&acc1[r];
        *(float4*)&out[(size_t)(r0 + r) * NSAMP + n] =
            make_float4(lo.x, lo.y, hi.x, hi.y);
    }
}

// ---------------- launch ----------------
extern "C" void kernel_launch(void* const* d_in, const int* in_sizes, int n_in,
                              void* d_out, int out_size) {
    const float* x     = (const float*)d_in[0];
    const float* w1r   = (const float*)d_in[1];
    const float* w1i   = (const float*)d_in[2];
    const float* gw    = (const float*)d_in[3];
    const float* gamma = (const float*)d_in[4];
    const float* beta  = (const float*)d_in[5];
    float* out = (float*)d_out;

    k_setup_F<<<(NSAMP * KDIM + 255) / 256, 256>>>();
    k_setup_W<<<1, 256>>>();
    k_setup_A<<<(NNODES * MODES + 255) / 256, 256>>>();
    k_transpose_w1<<<(MODES * CH * CH + 255) / 256, 256>>>(w1r, w1i);
    k_forward<<<dim3(ROWS / 64, KSPLIT), 256>>>(x);
    k_mag<<<ROWS, NNODES>>>(x);
    k_ln_gate<<<BATCH, 256>>>(gw, gamma, beta);
    k_modes<<<dim3(BATCH, MODES), CH>>>();
    k_inverse<<<dim3(NSAMP / 1024, ROWS / 16), 256>>>(out);
}

// round 5
// speedup vs baseline: 5.7875x; 1.1214x over previous
#include <cuda_runtime.h>
#include <math.h>

#define NSAMP 8192
#define MODES 32
#define KDIM  64          // 32 cos + 32 sin columns
#define BATCH 32
#define CH    64
#define ROWS  2048        // BATCH*CH
#define LSEG  20
#define MCHEB 8
#define NNODES 160        // LSEG*MCHEB
#define KSPLIT 16

// packed f32x2 FMA (sm_103a FFMA2; PTX-only path)
#define FMA2(d, a, b, c) \
    asm("fma.rn.f32x2 %0, %1, %2, %3;" : "=l"(d) : "l"(a), "l"(b), "l"(c))

// ---------------- device scratch (no allocations allowed) ----------------
__device__ float  g_Ftab [NSAMP*KDIM];   // [n][k]  k<32: cos(2pi k n/N), k>=32: sin
__device__ float  g_FtabT[KDIM*NSAMP];   // [k][n]
__device__ float  g_Ar[NNODES*MODES];
__device__ float  g_Ai[NNODES*MODES];
__device__ int    g_nodeL[NNODES];
__device__ float  g_nodeWL[NNODES];
__device__ float  g_nodeWR[NNODES];
__device__ float  g_sfor[ROWS*KDIM];     // forward sums: xr = s[f], xi = -s[32+f]
__device__ float  g_norm[ROWS*MODES];    // layernormed CFT magnitude
__device__ float  g_gate[BATCH*CH*MODES];
__device__ float  g_coef[ROWS*KDIM];     // inverse coefficients
__device__ float  g_w1Tr[MODES*CH*CH];   // [f][i][o]
__device__ float  g_w1Ti[MODES*CH*CH];

// ---------------- setup: DFT twiddle tables, both layouts coalesced -------
__global__ void k_setup_F() {
    int idx = blockIdx.x * blockDim.x + threadIdx.x;
    if (idx < ROWS * KDIM) g_sfor[idx] = 0.0f;            // fold in the zeroing
    if (idx >= 2 * NSAMP * KDIM) return;
    int n, k;
    if (idx < NSAMP * KDIM) { n = idx >> 6; k = idx & 63; }          // Ftab layout
    else { int j = idx - NSAMP * KDIM; k = j >> 13; n = j & (NSAMP - 1); } // FtabT
    int kf = k & 31;
    int m = (n * kf) & (NSAMP - 1);                       // exact phase mod 2pi
    float xm = (float)m * (1.0f / 4096.0f);               // exact (pow2 denom)
    float v = (k < MODES) ? cospif(xm) : sinpif(xm);
    if (idx < NSAMP * KDIM) g_Ftab[idx] = v;
    else g_FtabT[idx - NSAMP * KDIM] = v;
}

// ---------------- setup: CFT quadrature (one block, mostly float) ---------
__global__ void k_setup_WA() {
    __shared__ float sWr[MCHEB * MODES], sWi[MCHEB * MODES];
    const int tid = threadIdx.x;                          // 256 threads
    const float PIf = 3.14159265358979323846f;
    {
        int kc = tid >> 5, f = tid & 31;                  // Chebyshev order, freq
        float Wr = 0.0f, Wi = 0.0f;
        for (int mp = 0; mp < MCHEB; mp++) {
            float chebp = -cosf((2.0f * mp + 1.0f) * PIf / (2.0f * MCHEB));
            float Tkm = cosf((float)kc * acosf(chebp));
            float ang = chebp * (float)f * (PIf / (float)LSEG);
            Wr += Tkm * cosf(ang);
            Wi += Tkm * (-sinf(ang));
        }
        float s = 1.0f / (2.0f * LSEG);
        sWr[tid] = Wr * s;
        sWi[tid] = Wi * s;
    }
    if (tid < NNODES) {                                   // keep nodes in double
        int l = tid / MCHEB, m = tid % MCHEB;
        double cheb = -cos((2.0 * m + 1.0) * 3.14159265358979323846 / (2.0 * MCHEB));
        double tseg = (double)l / LSEG + (1.0 / (2.0 * LSEG)) * (cheb + 1.0);
        int right = (int)ceil(tseg * (double)(NSAMP - 1)); // searchsorted over i/(N-1)
        if (right < 1) right = 1;
        if (right > NSAMP - 1) right = NSAMP - 1;
        int left = right - 1;
        double wr = tseg * (double)(NSAMP - 1) - (double)left;
        g_nodeL[tid]  = left;
        g_nodeWR[tid] = (float)wr;
        g_nodeWL[tid] = (float)(1.0 - wr);
    }
    __syncthreads();
    for (int idx = tid; idx < NNODES * MODES; idx += 256) {
        int j = idx >> 5, f = idx & 31;
        int l = j >> 3, mc = j & 7;                       // Chebyshev-order index
        float Wr = sWr[mc * MODES + f], Wi = sWi[mc * MODES + f];
        int r = (l * f) % LSEG;                           // exact reduction of l*f/L
        float ph = (float)r * (2.0f / (float)LSEG);       // phi/pi
        float cphi = cospif(ph), sphi = sinpif(ph);
        g_Ar[idx] =  Wr * cphi + Wi * sphi;
        g_Ai[idx] = -Wr * sphi + Wi * cphi;
    }
}

// ---------------- setup: transpose w1 to f-major ----------------
__global__ void k_transpose_w1(const float* __restrict__ wr, const float* __restrict__ wi) {
    int idx = blockIdx.x * blockDim.x + threadIdx.x;
    if (idx >= MODES * CH * CH) return;
    int f = idx / (CH * CH);
    int rem = idx % (CH * CH);
    int i = rem / CH, o = rem % CH;
    g_w1Tr[idx] = __ldg(&wr[(i * CH + o) * MODES + f]);
    g_w1Ti[idx] = __ldg(&wi[(i * CH + o) * MODES + f]);
}

// ---------------- forward: S[2048x64] = X[2048x8192] * Ftab[8192x64] ------
// BM=128, BN=64, BK=16, 256 thr, thread-tile 4 rows x 8 cols (4 f32x2 pairs)
__global__ __launch_bounds__(256) void k_forward(const float* __restrict__ x) {
    __shared__ float2 sXd[16][128];   // duplicated (v,v), 16KB
    __shared__ float  sF[16][64];     // 4KB
    const int m0 = blockIdx.x * 128;
    const int kbase = blockIdx.y * (NSAMP / KSPLIT);
    const int tid = threadIdx.x;
    const int tx = tid & 7, ty = tid >> 3;     // tx: col-group, ty: row-group (0..31)
    const int xr = tid >> 1;                   // load row (0..127)
    const int xk = (tid & 1) * 8;              // load k-offset (0 or 8)
    const int fk = tid >> 4;                   // F row (0..15)
    const int fc = (tid & 15) * 4;             // F col quad

    unsigned long long acc[4][4];
#pragma unroll
    for (int i = 0; i < 4; i++)
#pragma unroll
        for (int j = 0; j < 4; j++) acc[i][j] = 0ull;

    for (int kt = 0; kt < NSAMP / KSPLIT; kt += 16) {
        const int k0 = kbase + kt;
        float4 v0 = *(const float4*)&x[(size_t)(m0 + xr) * NSAMP + k0 + xk];
        float4 v1 = *(const float4*)&x[(size_t)(m0 + xr) * NSAMP + k0 + xk + 4];
        sXd[xk + 0][xr] = make_float2(v0.x, v0.x);
        sXd[xk + 1][xr] = make_float2(v0.y, v0.y);
        sXd[xk + 2][xr] = make_float2(v0.z, v0.z);
        sXd[xk + 3][xr] = make_float2(v0.w, v0.w);
        sXd[xk + 4][xr] = make_float2(v1.x, v1.x);
        sXd[xk + 5][xr] = make_float2(v1.y, v1.y);
        sXd[xk + 6][xr] = make_float2(v1.z, v1.z);
        sXd[xk + 7][xr] = make_float2(v1.w, v1.w);
        *(float4*)&sF[fk][fc] = *(const float4*)&g_Ftab[(size_t)(k0 + fk) * KDIM + fc];
        __syncthreads();
#pragma unroll
        for (int kk = 0; kk < 16; kk++) {
            float4 bq0 = *(const float4*)&sF[kk][tx * 8];
            float4 bq1 = *(const float4*)&sF[kk][tx * 8 + 4];
            unsigned long long b0 = *(unsigned long long*)&bq0.x;
            unsigned long long b1 = *(unsigned long long*)&bq0.z;
            unsigned long long b2 = *(unsigned long long*)&bq1.x;
            unsigned long long b3 = *(unsigned long long*)&bq1.z;
#pragma unroll
            for (int i = 0; i < 4; i++) {
                unsigned long long a =
                    *(const unsigned long long*)&sXd[kk][ty * 4 + i];
                FMA2(acc[i][0], a, b0, acc[i][0]);
                FMA2(acc[i][1], a, b1, acc[i][1]);
                FMA2(acc[i][2], a, b2, acc[i][2]);
                FMA2(acc[i][3], a, b3, acc[i][3]);
            }
        }
        __syncthreads();
    }
#pragma unroll
    for (int i = 0; i < 4; i++) {
#pragma unroll
        for (int jp = 0; jp < 4; jp++) {
            float2 v = *(float2*)&acc[i][jp];
            float* dst = &g_sfor[(size_t)(m0 + ty * 4 + i) * KDIM + tx * 8 + jp * 2];
            atomicAdd(dst + 0, v.x);
            atomicAdd(dst + 1, v.y);
        }
    }
}

// ---------------- CFT magnitude + fused LayerNorm ----------------
__global__ void k_mag(const float* __restrict__ x,
                      const float* __restrict__ gamma,
                      const float* __restrict__ beta) {
    __shared__ float v[NNODES];
    const int row = blockIdx.x;
    const int tid = threadIdx.x;
    if (tid < NNODES) {
        int l = g_nodeL[tid];
        v[tid] = g_nodeWL[tid] * x[(size_t)row * NSAMP + l]
               + g_nodeWR[tid] * x[(size_t)row * NSAMP + l + 1];
    }
    __syncthreads();
    if (tid < MODES) {
        float re = 0.0f, im = 0.0f;
#pragma unroll 8
        for (int j = 0; j < NNODES; j++) {
            float vv = v[j];
            re = fmaf(vv, __ldg(&g_Ar[j * MODES + tid]), re);
            im = fmaf(vv, __ldg(&g_Ai[j * MODES + tid]), im);
        }
        float mag = sqrtf(re * re + im * im);
        // warp-level LayerNorm over the 32 modes
        float mu = mag;
#pragma unroll
        for (int s = 16; s > 0; s >>= 1) mu += __shfl_xor_sync(0xffffffffu, mu, s);
        mu *= (1.0f / MODES);
        float d = mag - mu;
        float var = d * d;
#pragma unroll
        for (int s = 16; s > 0; s >>= 1) var += __shfl_xor_sync(0xffffffffu, var, s);
        var *= (1.0f / MODES);
        float inv = rsqrtf(var + 1e-5f);
        g_norm[(size_t)row * MODES + tid] = d * inv * gamma[tid] + beta[tid];
    }
}

// ---------------- 1x1 conv gate (one block per batch b) -------------------
__global__ void k_gate(const float* __restrict__ gate_w) {
    __shared__ float sg[CH * MODES];
    const int b = blockIdx.x;
    const int tid = threadIdx.x;
    for (int e = tid; e < CH * MODES; e += blockDim.x)
        sg[e] = g_norm[(size_t)b * CH * MODES + e];
    __syncthreads();
    for (int e = tid; e < CH * MODES; e += blockDim.x) {
        int o = e >> 5, f = e & 31;
        float z = 0.0f;
#pragma unroll 8
        for (int i = 0; i < CH; i++)
            z = fmaf(__ldg(&gate_w[o * CH + i]), sg[i * MODES + f], z);
        g_gate[(size_t)b * CH * MODES + e] = 1.0f / (1.0f + expf(-z));
    }
}

// -------- per-(b,f) 64x64 complex matvec + irfft coefficient prep ---------
__global__ void k_modes() {
    const int b = blockIdx.x, f = blockIdx.y;
    const int o = threadIdx.x;
    __shared__ float gr[CH], gi[CH];
    {
        int i = o;
        float g = g_gate[((size_t)b * CH + i) * MODES + f];
        gr[i] =  g_sfor[((size_t)b * CH + i) * KDIM + f] * g;          // xr * gate
        gi[i] = -g_sfor[((size_t)b * CH + i) * KDIM + MODES + f] * g;  // xi * gate
    }
    __syncthreads();
    float orr = 0.0f, oii = 0.0f;
    const float* wr = &g_w1Tr[(size_t)f * CH * CH];
    const float* wi = &g_w1Ti[(size_t)f * CH * CH];
#pragma unroll 8
    for (int i = 0; i < CH; i++) {
        float a = gr[i], c = gi[i];
        float xr = wr[i * CH + o], xi = wi[i * CH + o];
        orr = fmaf(a, xr, orr); orr = fmaf(-c, xi, orr);
        oii = fmaf(a, xi, oii); oii = fmaf( c, xr, oii);
    }
    // irfft of 32-mode-truncated spectrum; imag of bin 0 ignored by hc2r
    float sc = (f == 0) ? (1.0f / NSAMP) : (2.0f / NSAMP);
    int row = b * CH + o;
    g_coef[(size_t)row * KDIM + f] = sc * orr;
    g_coef[(size_t)row * KDIM + MODES + f] = (f == 0) ? 0.0f : (-sc * oii);
}

// ---------------- inverse: out = coef[2048x64] * FtabT[64x8192] -----------
// block: 64 rows x 256 cols; 256 threads; thread-tile 8 rows x 8 cols.
__global__ __launch_bounds__(256, 1) void k_inverse(float* __restrict__ out) {
    __shared__ float2 sctd[KDIM][KDIM];   // [k][row] duplicated (v,v), 32KB
    const int n0 = blockIdx.x * 256;
    const int r0 = blockIdx.y * 64;
    const int tid = threadIdx.x;
    const int tx = tid & 31, ty = tid >> 5;   // tx: col group, ty: row group (0..7)
    // load coef tile: 64 rows x 64 k = 1024 float4, 4 per thread
#pragma unroll
    for (int t = 0; t < 4; t++) {
        int f4 = tid + t * 256;
        int r = f4 >> 4, c0 = (f4 & 15) * 4;
        float4 v = *(const float4*)&g_coef[(size_t)(r0 + r) * KDIM + c0];
        sctd[c0 + 0][r] = make_float2(v.x, v.x);
        sctd[c0 + 1][r] = make_float2(v.y, v.y);
        sctd[c0 + 2][r] = make_float2(v.z, v.z);
        sctd[c0 + 3][r] = make_float2(v.w, v.w);
    }
    __syncthreads();
    const int n = n0 + tx * 8;
    unsigned long long acc[8][4];
#pragma unroll
    for (int r = 0; r < 8; r++)
#pragma unroll
        for (int j = 0; j < 4; j++) acc[r][j] = 0ull;

    for (int k = 0; k < KDIM; k++) {
        float4 f0 = *(const float4*)&g_FtabT[(size_t)k * NSAMP + n];
        float4 f1 = *(const float4*)&g_FtabT[(size_t)k * NSAMP + n + 4];
        unsigned long long fa0 = *(unsigned long long*)&f0.x;
        unsigned long long fa1 = *(unsigned long long*)&f0.z;
        unsigned long long fa2 = *(unsigned long long*)&f1.x;
        unsigned long long fa3 = *(unsigned long long*)&f1.z;
#pragma unroll
        for (int r = 0; r < 8; r++) {
            unsigned long long c = *(const unsigned long long*)&sctd[k][ty * 8 + r];
            FMA2(acc[r][0], fa0, c, acc[r][0]);
            FMA2(acc[r][1], fa1, c, acc[r][1]);
            FMA2(acc[r][2], fa2, c, acc[r][2]);
            FMA2(acc[r][3], fa3, c, acc[r][3]);
        }
    }
#pragma unroll
    for (int r = 0; r < 8; r++) {
        float2 p0 = *(float2*)&acc[r][0];
        float2 p1 = *(float2*)&acc[r][1];
        float2 p2 = *(float2*)&acc[r][2];
        float2 p3 = *(float2*)&acc[r][3];
        float* dst = &out[(size_t)(r0 + ty * 8 + r) * NSAMP + n];
        *(float4*)dst       = make_float4(p0.x, p0.y, p1.x, p1.y);
        *(float4*)(dst + 4) = make_float4(p2.x, p2.y, p3.x, p3.y);
    }
}

// ---------------- launch ----------------
extern "C" void kernel_launch(void* const* d_in, const int* in_sizes, int n_in,
                              void* d_out, int out_size) {
    const float* x     = (const float*)d_in[0];
    const float* w1r   = (const float*)d_in[1];
    const float* w1i   = (const float*)d_in[2];
    const float* gw    = (const float*)d_in[3];
    const float* gamma = (const float*)d_in[4];
    const float* beta  = (const float*)d_in[5];
    float* out = (float*)d_out;

    k_setup_F<<<(2 * NSAMP * KDIM + 255) / 256, 256>>>();
    k_setup_WA<<<1, 256>>>();
    k_transpose_w1<<<(MODES * CH * CH + 255) / 256, 256>>>(w1r, w1i);
    k_forward<<<dim3(ROWS / 128, KSPLIT), 256>>>(x);
    k_mag<<<ROWS, NNODES>>>(x, gamma, beta);
    k_gate<<<BATCH, 256>>>(gw);
    k_modes<<<dim3(BATCH, MODES), CH>>>();
    k_inverse<<<dim3(NSAMP / 256, ROWS / 64), 256>>>(out);
}

// round 6
// speedup vs baseline: 6.2901x; 1.0868x over previous
#include <cuda_runtime.h>
#include <math.h>

#define NSAMP 8192
#define MODES 32
#define KDIM  64          // 32 cos + 32 sin columns
#define BATCH 32
#define CH    64
#define ROWS  2048        // BATCH*CH
#define LSEG  20
#define MCHEB 8
#define NNODES 160        // LSEG*MCHEB
#define KSPLIT 32

typedef unsigned long long ull;

// packed f32x2 FMA (sm_103a FFMA2; PTX-only path)
#define FMA2(d, a, b, c) \
    asm("fma.rn.f32x2 %0, %1, %2, %3;" : "=l"(d) : "l"(a), "l"(b), "l"(c))
// duplicate a scalar float into both lanes of a packed f32x2
#define PACKDUP(d, v) \
    asm("mov.b64 %0, {%1, %1};" : "=l"(d) : "r"(__float_as_uint(v)))

// ---------------- device scratch (no allocations allowed) ----------------
__device__ float  g_Ftab [NSAMP*KDIM];   // [n][k]  k<32: cos(2pi k n/N), k>=32: sin
__device__ float  g_FtabT[KDIM*NSAMP];   // [k][n]
__device__ float  g_Ar[NNODES*MODES];
__device__ float  g_Ai[NNODES*MODES];
__device__ int    g_nodeL[NNODES];
__device__ float  g_nodeWL[NNODES];
__device__ float  g_nodeWR[NNODES];
__device__ float  g_sfor[ROWS*KDIM];     // forward sums: xr = s[f], xi = -s[32+f]
__device__ float  g_norm[ROWS*MODES];    // layernormed CFT magnitude
__device__ float  g_gate[BATCH*CH*MODES];
__device__ float  g_coef[ROWS*KDIM];     // inverse coefficients
__device__ float  g_w1Tr[MODES*CH*CH];   // [f][i][o]
__device__ float  g_w1Ti[MODES*CH*CH];

// ---------------- setup: DFT twiddle tables, both layouts coalesced -------
__global__ void k_setup_F() {
    int idx = blockIdx.x * blockDim.x + threadIdx.x;
    if (idx < ROWS * KDIM) g_sfor[idx] = 0.0f;            // fold in the zeroing
    if (idx >= 2 * NSAMP * KDIM) return;
    int n, k;
    if (idx < NSAMP * KDIM) { n = idx >> 6; k = idx & 63; }          // Ftab layout
    else { int j = idx - NSAMP * KDIM; k = j >> 13; n = j & (NSAMP - 1); } // FtabT
    int kf = k & 31;
    int m = (n * kf) & (NSAMP - 1);                       // exact phase mod 2pi
    float xm = (float)m * (1.0f / 4096.0f);               // exact (pow2 denom)
    float v = (k < MODES) ? cospif(xm) : sinpif(xm);
    if (idx < NSAMP * KDIM) g_Ftab[idx] = v;
    else g_FtabT[idx - NSAMP * KDIM] = v;
}

// ---------------- setup: CFT quadrature (one block, mostly float) ---------
__global__ void k_setup_WA() {
    __shared__ float sWr[MCHEB * MODES], sWi[MCHEB * MODES];
    const int tid = threadIdx.x;                          // 256 threads
    const float PIf = 3.14159265358979323846f;
    {
        int kc = tid >> 5, f = tid & 31;                  // Chebyshev order, freq
        float Wr = 0.0f, Wi = 0.0f;
        for (int mp = 0; mp < MCHEB; mp++) {
            float chebp = -cosf((2.0f * mp + 1.0f) * PIf / (2.0f * MCHEB));
            float Tkm = cosf((float)kc * acosf(chebp));
            float ang = chebp * (float)f * (PIf / (float)LSEG);
            Wr += Tkm * cosf(ang);
            Wi += Tkm * (-sinf(ang));
        }
        float s = 1.0f / (2.0f * LSEG);
        sWr[tid] = Wr * s;
        sWi[tid] = Wi * s;
    }
    if (tid < NNODES) {                                   // keep nodes in double
        int l = tid / MCHEB, m = tid % MCHEB;
        double cheb = -cos((2.0 * m + 1.0) * 3.14159265358979323846 / (2.0 * MCHEB));
        double tseg = (double)l / LSEG + (1.0 / (2.0 * LSEG)) * (cheb + 1.0);
        int right = (int)ceil(tseg * (double)(NSAMP - 1)); // searchsorted over i/(N-1)
        if (right < 1) right = 1;
        if (right > NSAMP - 1) right = NSAMP - 1;
        int left = right - 1;
        double wr = tseg * (double)(NSAMP - 1) - (double)left;
        g_nodeL[tid]  = left;
        g_nodeWR[tid] = (float)wr;
        g_nodeWL[tid] = (float)(1.0 - wr);
    }
    __syncthreads();
    for (int idx = tid; idx < NNODES * MODES; idx += 256) {
        int j = idx >> 5, f = idx & 31;
        int l = j >> 3, mc = j & 7;                       // Chebyshev-order index
        float Wr = sWr[mc * MODES + f], Wi = sWi[mc * MODES + f];
        int r = (l * f) % LSEG;                           // exact reduction of l*f/L
        float ph = (float)r * (2.0f / (float)LSEG);       // phi/pi
        float cphi = cospif(ph), sphi = sinpif(ph);
        g_Ar[idx] =  Wr * cphi + Wi * sphi;
        g_Ai[idx] = -Wr * sphi + Wi * cphi;
    }
}

// ---------------- setup: transpose w1 to f-major (tiled, coalesced) -------
__global__ void k_transpose_w1(const float* __restrict__ wr, const float* __restrict__ wi) {
    __shared__ float tr[32][33], ti[32][33];
    const int rbase = blockIdx.x * 32;    // 128 blocks over r = i*64+o (4096)
    const int t = threadIdx.x;            // 256
    {
        int f = t & 31, rr = t >> 5;
#pragma unroll
        for (int s = 0; s < 4; s++) {
            int r = rr + s * 8;
            tr[r][f] = __ldg(&wr[(size_t)(rbase + r) * MODES + f]);
            ti[r][f] = __ldg(&wi[(size_t)(rbase + r) * MODES + f]);
        }
    }
    __syncthreads();
    {
        int r = t & 31, ff = t >> 5;
#pragma unroll
        for (int s = 0; s < 4; s++) {
            int f = ff + s * 8;
            g_w1Tr[(size_t)f * (CH * CH) + rbase + r] = tr[r][f];
            g_w1Ti[(size_t)f * (CH * CH) + rbase + r] = ti[r][f];
        }
    }
}

// ---------------- forward: S[2048x64] = X[2048x8192] * Ftab[8192x64] ------
// BM=128, BN=64, BK=16. 256 thr, thread-tile 8 rows (4 M-pairs) x 4 cols.
// Double-buffered smem, register prefetch one tile ahead.
__global__ __launch_bounds__(256) void k_forward(const float* __restrict__ x) {
    __shared__ float  sX[2][16][128];   // [buf][kk][m] plain, 8KB each
    __shared__ float2 sFd[2][16][64];   // [buf][kk][n] duplicated, 8KB each
    const int m0 = blockIdx.x * 128;
    const int kbase = blockIdx.y * (NSAMP / KSPLIT);    // 256-wide window
    const int tid = threadIdx.x;
    const int tx = tid & 15, ty = tid >> 4;   // cols tx*4.., rows ty*8..
    const int xr = tid >> 1;                  // load row (0..127)
    const int xk = (tid & 1) * 8;             // load k-offset (0 or 8)
    const int fk = tid >> 4;                  // F row (0..15)
    const int fc = (tid & 15) * 4;            // F col quad
    const int NT = (NSAMP / KSPLIT) / 16;     // 16 tiles

    float rx[8]; float4 rf;
    // load tile 0
    {
        const float* px = &x[(size_t)(m0 + xr) * NSAMP + kbase + xk];
        float4 v0 = *(const float4*)px;
        float4 v1 = *(const float4*)(px + 4);
        rx[0]=v0.x; rx[1]=v0.y; rx[2]=v0.z; rx[3]=v0.w;
        rx[4]=v1.x; rx[5]=v1.y; rx[6]=v1.z; rx[7]=v1.w;
        rf = *(const float4*)&g_Ftab[(size_t)(kbase + fk) * KDIM + fc];
    }
    // store tile 0 -> buf 0
#pragma unroll
    for (int j = 0; j < 8; j++) sX[0][xk + j][xr] = rx[j];
    sFd[0][fk][fc + 0] = make_float2(rf.x, rf.x);
    sFd[0][fk][fc + 1] = make_float2(rf.y, rf.y);
    sFd[0][fk][fc + 2] = make_float2(rf.z, rf.z);
    sFd[0][fk][fc + 3] = make_float2(rf.w, rf.w);
    // load tile 1
    {
        const int k0 = kbase + 16;
        const float* px = &x[(size_t)(m0 + xr) * NSAMP + k0 + xk];
        float4 v0 = *(const float4*)px;
        float4 v1 = *(const float4*)(px + 4);
        rx[0]=v0.x; rx[1]=v0.y; rx[2]=v0.z; rx[3]=v0.w;
        rx[4]=v1.x; rx[5]=v1.y; rx[6]=v1.z; rx[7]=v1.w;
        rf = *(const float4*)&g_Ftab[(size_t)(k0 + fk) * KDIM + fc];
    }
    __syncthreads();

    ull acc[4][4];
#pragma unroll
    for (int i = 0; i < 4; i++)
#pragma unroll
        for (int j = 0; j < 4; j++) acc[i][j] = 0ull;

    for (int kt = 0; kt < NT; kt++) {
        const int buf = kt & 1;
        if (kt + 1 < NT) {
            const int nb = buf ^ 1;
#pragma unroll
            for (int j = 0; j < 8; j++) sX[nb][xk + j][xr] = rx[j];
            sFd[nb][fk][fc + 0] = make_float2(rf.x, rf.x);
            sFd[nb][fk][fc + 1] = make_float2(rf.y, rf.y);
            sFd[nb][fk][fc + 2] = make_float2(rf.z, rf.z);
            sFd[nb][fk][fc + 3] = make_float2(rf.w, rf.w);
            if (kt + 2 < NT) {
                const int k0 = kbase + (kt + 2) * 16;
                const float* px = &x[(size_t)(m0 + xr) * NSAMP + k0 + xk];
                float4 v0 = *(const float4*)px;
                float4 v1 = *(const float4*)(px + 4);
                rx[0]=v0.x; rx[1]=v0.y; rx[2]=v0.z; rx[3]=v0.w;
                rx[4]=v1.x; rx[5]=v1.y; rx[6]=v1.z; rx[7]=v1.w;
                rf = *(const float4*)&g_Ftab[(size_t)(k0 + fk) * KDIM + fc];
            }
        }
        const float  (*pX)[128] = sX[buf];
        const float2 (*pF)[64]  = sFd[buf];
#pragma unroll
        for (int kk = 0; kk < 16; kk++) {
            float4 av0 = *(const float4*)&pX[kk][ty * 8];
            float4 av1 = *(const float4*)&pX[kk][ty * 8 + 4];
            ull a0 = *(ull*)&av0.x, a1 = *(ull*)&av0.z;
            ull a2 = *(ull*)&av1.x, a3 = *(ull*)&av1.z;
            float4 bv0 = *(const float4*)&pF[kk][tx * 4];
            float4 bv1 = *(const float4*)&pF[kk][tx * 4 + 2];
            ull b0 = *(ull*)&bv0.x, b1 = *(ull*)&bv0.z;
            ull b2 = *(ull*)&bv1.x, b3 = *(ull*)&bv1.z;
            FMA2(acc[0][0], a0, b0, acc[0][0]); FMA2(acc[0][1], a0, b1, acc[0][1]);
            FMA2(acc[0][2], a0, b2, acc[0][2]); FMA2(acc[0][3], a0, b3, acc[0][3]);
            FMA2(acc[1][0], a1, b0, acc[1][0]); FMA2(acc[1][1], a1, b1, acc[1][1]);
            FMA2(acc[1][2], a1, b2, acc[1][2]); FMA2(acc[1][3], a1, b3, acc[1][3]);
            FMA2(acc[2][0], a2, b0, acc[2][0]); FMA2(acc[2][1], a2, b1, acc[2][1]);
            FMA2(acc[2][2], a2, b2, acc[2][2]); FMA2(acc[2][3], a2, b3, acc[2][3]);
            FMA2(acc[3][0], a3, b0, acc[3][0]); FMA2(acc[3][1], a3, b1, acc[3][1]);
            FMA2(acc[3][2], a3, b2, acc[3][2]); FMA2(acc[3][3], a3, b3, acc[3][3]);
        }
        __syncthreads();
    }
    // acc[i][j]: rows (m0+ty*8+2i, +1), col tx*4+j
#pragma unroll
    for (int i = 0; i < 4; i++)
#pragma unroll
        for (int j = 0; j < 4; j++) {
            float2 v = *(float2*)&acc[i][j];
            atomicAdd(&g_sfor[(size_t)(m0 + ty * 8 + 2 * i) * KDIM + tx * 4 + j], v.x);
            atomicAdd(&g_sfor[(size_t)(m0 + ty * 8 + 2 * i + 1) * KDIM + tx * 4 + j], v.y);
        }
}

// ---------------- CFT magnitude + fused LayerNorm (256 thr, split dot) ----
__global__ void k_mag(const float* __restrict__ x,
                      const float* __restrict__ gamma,
                      const float* __restrict__ beta) {
    __shared__ float v[NNODES];
    __shared__ float pre[8][MODES], pim[8][MODES];
    const int row = blockIdx.x;
    const int tid = threadIdx.x;
    if (tid < NNODES) {
        int l = g_nodeL[tid];
        v[tid] = g_nodeWL[tid] * x[(size_t)row * NSAMP + l]
               + g_nodeWR[tid] * x[(size_t)row * NSAMP + l + 1];
    }
    __syncthreads();
    {
        const int w = tid >> 5, f = tid & 31;
        float re = 0.0f, im = 0.0f;
        const int j0 = w * 20;
#pragma unroll
        for (int j = 0; j < 20; j++) {
            float vv = v[j0 + j];
            re = fmaf(vv, __ldg(&g_Ar[(j0 + j) * MODES + f]), re);
            im = fmaf(vv, __ldg(&g_Ai[(j0 + j) * MODES + f]), im);
        }
        pre[w][f] = re; pim[w][f] = im;
    }
    __syncthreads();
    if (tid < MODES) {
        float re = 0.0f, im = 0.0f;
#pragma unroll
        for (int w = 0; w < 8; w++) { re += pre[w][tid]; im += pim[w][tid]; }
        float mag = sqrtf(re * re + im * im);
        float mu = mag;
#pragma unroll
        for (int s = 16; s > 0; s >>= 1) mu += __shfl_xor_sync(0xffffffffu, mu, s);
        mu *= (1.0f / MODES);
        float d = mag - mu;
        float var = d * d;
#pragma unroll
        for (int s = 16; s > 0; s >>= 1) var += __shfl_xor_sync(0xffffffffu, var, s);
        var *= (1.0f / MODES);
        float inv = rsqrtf(var + 1e-5f);
        g_norm[(size_t)row * MODES + tid] = d * inv * gamma[tid] + beta[tid];
    }
}

// ---------------- 1x1 conv gate (one block per batch b) -------------------
__global__ void k_gate(const float* __restrict__ gate_w) {
    __shared__ float sg[CH * MODES];
    const int b = blockIdx.x;
    const int tid = threadIdx.x;
    for (int e = tid; e < CH * MODES; e += blockDim.x)
        sg[e] = g_norm[(size_t)b * CH * MODES + e];
    __syncthreads();
    for (int e = tid; e < CH * MODES; e += blockDim.x) {
        int o = e >> 5, f = e & 31;
        float z = 0.0f;
#pragma unroll 8
        for (int i = 0; i < CH; i++)
            z = fmaf(__ldg(&gate_w[o * CH + i]), sg[i * MODES + f], z);
        g_gate[(size_t)b * CH * MODES + e] = 1.0f / (1.0f + expf(-z));
    }
}

// -------- per-(b,f) 64x64 complex matvec + irfft coefficient prep ---------
__global__ void k_modes() {
    const int b = blockIdx.x, f = blockIdx.y;
    const int o = threadIdx.x;
    __shared__ float gr[CH], gi[CH];
    {
        int i = o;
        float g = g_gate[((size_t)b * CH + i) * MODES + f];
        gr[i] =  g_sfor[((size_t)b * CH + i) * KDIM + f] * g;          // xr * gate
        gi[i] = -g_sfor[((size_t)b * CH + i) * KDIM + MODES + f] * g;  // xi * gate
    }
    __syncthreads();
    float orr = 0.0f, oii = 0.0f;
    const float* wr = &g_w1Tr[(size_t)f * CH * CH];
    const float* wi = &g_w1Ti[(size_t)f * CH * CH];
#pragma unroll 8
    for (int i = 0; i < CH; i++) {
        float a = gr[i], c = gi[i];
        float xr = wr[i * CH + o], xi = wi[i * CH + o];
        orr = fmaf(a, xr, orr); orr = fmaf(-c, xi, orr);
        oii = fmaf(a, xi, oii); oii = fmaf( c, xr, oii);
    }
    // irfft of 32-mode-truncated spectrum; imag of bin 0 ignored by hc2r
    float sc = (f == 0) ? (1.0f / NSAMP) : (2.0f / NSAMP);
    int row = b * CH + o;
    g_coef[(size_t)row * KDIM + f] = sc * orr;
    g_coef[(size_t)row * KDIM + MODES + f] = (f == 0) ? 0.0f : (-sc * oii);
}

// ---------------- inverse: out = coef[2048x64] * FtabT[64x8192] -----------
// block: 32 rows x 256 cols; 256 threads; thread-tile 4 rows x 8 cols.
// coef tile in plain smem; a-dup built with mov.b64 (ALU pipe, overlaps fma).
__global__ __launch_bounds__(256) void k_inverse(float* __restrict__ out) {
    __shared__ float sct[32][KDIM + 4];     // [r][k] plain, padded
    const int n0 = blockIdx.x * 256;
    const int r0 = blockIdx.y * 32;
    const int tid = threadIdx.x;
    const int tx = tid & 31, ty = tid >> 5;   // cols tx*8.., rows ty*4..
    {
        int r = tid >> 3, c0 = (tid & 7) * 8;
        float4 v0 = *(const float4*)&g_coef[(size_t)(r0 + r) * KDIM + c0];
        float4 v1 = *(const float4*)&g_coef[(size_t)(r0 + r) * KDIM + c0 + 4];
        *(float4*)&sct[r][c0]     = v0;
        *(float4*)&sct[r][c0 + 4] = v1;
    }
    __syncthreads();
    const int n = n0 + tx * 8;
    ull acc[4][4];
#pragma unroll
    for (int i = 0; i < 4; i++)
#pragma unroll
        for (int j = 0; j < 4; j++) acc[i][j] = 0ull;

#pragma unroll 4
    for (int k = 0; k < KDIM; k++) {
        float4 f0 = *(const float4*)&g_FtabT[(size_t)k * NSAMP + n];
        float4 f1 = *(const float4*)&g_FtabT[(size_t)k * NSAMP + n + 4];
        ull b0 = *(ull*)&f0.x, b1 = *(ull*)&f0.z;
        ull b2 = *(ull*)&f1.x, b3 = *(ull*)&f1.z;
        ull a0, a1, a2, a3;
        PACKDUP(a0, sct[ty * 4 + 0][k]);
        PACKDUP(a1, sct[ty * 4 + 1][k]);
        PACKDUP(a2, sct[ty * 4 + 2][k]);
        PACKDUP(a3, sct[ty * 4 + 3][k]);
        FMA2(acc[0][0], b0, a0, acc[0][0]); FMA2(acc[0][1], b1, a0, acc[0][1]);
        FMA2(acc[0][2], b2, a0, acc[0][2]); FMA2(acc[0][3], b3, a0, acc[0][3]);
        FMA2(acc[1][0], b0, a1, acc[1][0]); FMA2(acc[1][1], b1, a1, acc[1][1]);
        FMA2(acc[1][2], b2, a1, acc[1][2]); FMA2(acc[1][3], b3, a1, acc[1][3]);
        FMA2(acc[2][0], b0, a2, acc[2][0]); FMA2(acc[2][1], b1, a2, acc[2][1]);
        FMA2(acc[2][2], b2, a2, acc[2][2]); FMA2(acc[2][3], b3, a2, acc[2][3]);
        FMA2(acc[3][0], b0, a3, acc[3][0]); FMA2(acc[3][1], b1, a3, acc[3][1]);
        FMA2(acc[3][2], b2, a3, acc[3][2]); FMA2(acc[3][3], b3, a3, acc[3][3]);
    }
#pragma unroll
    for (int i = 0; i < 4; i++) {
        float2 p0 = *(float2*)&acc[i][0];
        float2 p1 = *(float2*)&acc[i][1];
        float2 p2 = *(float2*)&acc[i][2];
        float2 p3 = *(float2*)&acc[i][3];
        float* dst = &out[(size_t)(r0 + ty * 4 + i) * NSAMP + n];
        *(float4*)dst       = make_float4(p0.x, p0.y, p1.x, p1.y);
        *(float4*)(dst + 4) = make_float4(p2.x, p2.y, p3.x, p3.y);
    }
}

// ---------------- launch ----------------
extern "C" void kernel_launch(void* const* d_in, const int* in_sizes, int n_in,
                              void* d_out, int out_size) {
    const float* x     = (const float*)d_in[0];
    const float* w1r   = (const float*)d_in[1];
    const float* w1i   = (const float*)d_in[2];
    const float* gw    = (const float*)d_in[3];
    const float* gamma = (const float*)d_in[4];
    const float* beta  = (const float*)d_in[5];
    float* out = (float*)d_out;

    k_setup_F<<<(2 * NSAMP * KDIM + 255) / 256, 256>>>();
    k_setup_WA<<<1, 256>>>();
    k_transpose_w1<<<CH * CH / 32, 256>>>(w1r, w1i);
    k_forward<<<dim3(ROWS / 128, KSPLIT), 256>>>(x);
    k_mag<<<ROWS, 256>>>(x, gamma, beta);
    k_gate<<<BATCH, 256>>>(gw);
    k_modes<<<dim3(BATCH, MODES), CH>>>();
    k_inverse<<<dim3(NSAMP / 256, ROWS / 32), 256>>>(out);
}

// round 7
// speedup vs baseline: 6.6098x; 1.0508x over previous
#include <cuda_runtime.h>
#include <math.h>

#define NSAMP 8192
#define MODES 32
#define KDIM  64          // 32 cos + 32 sin columns
#define BATCH 32
#define CH    64
#define ROWS  2048        // BATCH*CH
#define LSEG  20
#define MCHEB 8
#define NNODES 160        // LSEG*MCHEB
#define KSPLIT 32

typedef unsigned long long ull;

// packed f32x2 FMA (sm_103a FFMA2; PTX-only path)
#define FMA2(d, a, b, c) \
    asm("fma.rn.f32x2 %0, %1, %2, %3;" : "=l"(d) : "l"(a), "l"(b), "l"(c))
// duplicate a scalar float into both lanes of a packed f32x2
#define PACKDUP(d, v) \
    asm("mov.b64 %0, {%1, %1};" : "=l"(d) : "r"(__float_as_uint(v)))

// ---------------- device scratch (no allocations allowed) ----------------
__device__ float  g_Ftab [NSAMP*KDIM];   // [n][k]  k<32: cos(2pi k n/N), k>=32: sin
__device__ float  g_FtabT[KDIM*NSAMP];   // [k][n]
__device__ float  g_part [KSPLIT*ROWS*KDIM];  // forward k-split partials (16MB)
__device__ float  g_Ar[NNODES*MODES];
__device__ float  g_Ai[NNODES*MODES];
__device__ int    g_nodeL[NNODES];
__device__ float  g_nodeWL[NNODES];
__device__ float  g_nodeWR[NNODES];
__device__ float  g_sfor[ROWS*KDIM];     // forward sums: xr = s[f], xi = -s[32+f]
__device__ float  g_norm[ROWS*MODES];    // layernormed CFT magnitude
__device__ float  g_gate[BATCH*CH*MODES];
__device__ float  g_coef[ROWS*KDIM];     // inverse coefficients
__device__ float  g_w1Tr[MODES*CH*CH];   // [f][i][o]
__device__ float  g_w1Ti[MODES*CH*CH];

// ---------------- setup: DFT twiddle tables, both layouts coalesced -------
__global__ void k_setup_F() {
    int idx = blockIdx.x * blockDim.x + threadIdx.x;
    if (idx >= 2 * NSAMP * KDIM) return;
    int n, k;
    if (idx < NSAMP * KDIM) { n = idx >> 6; k = idx & 63; }          // Ftab layout
    else { int j = idx - NSAMP * KDIM; k = j >> 13; n = j & (NSAMP - 1); } // FtabT
    int kf = k & 31;
    int m = (n * kf) & (NSAMP - 1);                       // exact phase mod 2pi
    float xm = (float)m * (1.0f / 4096.0f);               // exact (pow2 denom)
    float v = (k < MODES) ? cospif(xm) : sinpif(xm);
    if (idx < NSAMP * KDIM) g_Ftab[idx] = v;
    else g_FtabT[idx - NSAMP * KDIM] = v;
}

// ---------------- setup: CFT quadrature (one block, mostly float) ---------
__global__ void k_setup_WA() {
    __shared__ float sWr[MCHEB * MODES], sWi[MCHEB * MODES];
    const int tid = threadIdx.x;                          // 256 threads
    const float PIf = 3.14159265358979323846f;
    {
        int kc = tid >> 5, f = tid & 31;                  // Chebyshev order, freq
        float Wr = 0.0f, Wi = 0.0f;
        for (int mp = 0; mp < MCHEB; mp++) {
            float chebp = -cosf((2.0f * mp + 1.0f) * PIf / (2.0f * MCHEB));
            float Tkm = cosf((float)kc * acosf(chebp));
            float ang = chebp * (float)f * (PIf / (float)LSEG);
            Wr += Tkm * cosf(ang);
            Wi += Tkm * (-sinf(ang));
        }
        float s = 1.0f / (2.0f * LSEG);
        sWr[tid] = Wr * s;
        sWi[tid] = Wi * s;
    }
    if (tid < NNODES) {                                   // keep nodes in double
        int l = tid / MCHEB, m = tid % MCHEB;
        double cheb = -cos((2.0 * m + 1.0) * 3.14159265358979323846 / (2.0 * MCHEB));
        double tseg = (double)l / LSEG + (1.0 / (2.0 * LSEG)) * (cheb + 1.0);
        int right = (int)ceil(tseg * (double)(NSAMP - 1)); // searchsorted over i/(N-1)
        if (right < 1) right = 1;
        if (right > NSAMP - 1) right = NSAMP - 1;
        int left = right - 1;
        double wr = tseg * (double)(NSAMP - 1) - (double)left;
        g_nodeL[tid]  = left;
        g_nodeWR[tid] = (float)wr;
        g_nodeWL[tid] = (float)(1.0 - wr);
    }
    __syncthreads();
    for (int idx = tid; idx < NNODES * MODES; idx += 256) {
        int j = idx >> 5, f = idx & 31;
        int l = j >> 3, mc = j & 7;                       // Chebyshev-order index
        float Wr = sWr[mc * MODES + f], Wi = sWi[mc * MODES + f];
        int r = (l * f) % LSEG;                           // exact reduction of l*f/L
        float ph = (float)r * (2.0f / (float)LSEG);       // phi/pi
        float cphi = cospif(ph), sphi = sinpif(ph);
        g_Ar[idx] =  Wr * cphi + Wi * sphi;
        g_Ai[idx] = -Wr * sphi + Wi * cphi;
    }
}

// ---------------- setup: transpose w1 to f-major (tiled, coalesced) -------
__global__ void k_transpose_w1(const float* __restrict__ wr, const float* __restrict__ wi) {
    __shared__ float tr[32][33], ti[32][33];
    const int rbase = blockIdx.x * 32;    // 128 blocks over r = i*64+o (4096)
    const int t = threadIdx.x;            // 256
    {
        int f = t & 31, rr = t >> 5;
#pragma unroll
        for (int s = 0; s < 4; s++) {
            int r = rr + s * 8;
            tr[r][f] = __ldg(&wr[(size_t)(rbase + r) * MODES + f]);
            ti[r][f] = __ldg(&wi[(size_t)(rbase + r) * MODES + f]);
        }
    }
    __syncthreads();
    {
        int r = t & 31, ff = t >> 5;
#pragma unroll
        for (int s = 0; s < 4; s++) {
            int f = ff + s * 8;
            g_w1Tr[(size_t)f * (CH * CH) + rbase + r] = tr[r][f];
            g_w1Ti[(size_t)f * (CH * CH) + rbase + r] = ti[r][f];
        }
    }
}

// ---------------- forward: S[2048x64] = X[2048x8192] * Ftab[8192x64] ------
// grid (16, 32). BM=128, per-block k-range 256 (two 128-halves).
// X never touches smem: warp-broadcast LDG + register double buffer.
// Thread tile: 4 rows x 8 cols (cols as 4 natural f32x2 pairs).
__global__ __launch_bounds__(256) void k_forward(const float* __restrict__ x) {
    __shared__ float sF[128][64];   // 32KB: half of this block's F slice
    const int m0 = blockIdx.x * 128;
    const int kbase = blockIdx.y * 256;
    const int tid = threadIdx.x;
    const int tx = tid & 7;          // col group: cols tx*8..+7
    const int ty = tid >> 3;         // row group: rows ty*4..+3
    const float* xr0 = x + (size_t)(m0 + ty * 4 + 0) * NSAMP + kbase;
    const float* xr1 = xr0 + NSAMP;
    const float* xr2 = xr1 + NSAMP;
    const float* xr3 = xr2 + NSAMP;

    ull acc[4][4];
#pragma unroll
    for (int r = 0; r < 4; r++)
#pragma unroll
        for (int j = 0; j < 4; j++) acc[r][j] = 0ull;

#pragma unroll 1
    for (int half = 0; half < 2; half++) {
        const int koff = half * 128;
        __syncthreads();
#pragma unroll
        for (int t = 0; t < 8; t++) {
            int e = tid + t * 256;
            int kk = e >> 4, ff = (e & 15) * 4;
            *(float4*)&sF[kk][ff] =
                *(const float4*)&g_Ftab[(size_t)(kbase + koff + kk) * KDIM + ff];
        }
        __syncthreads();

        float4 cur[4], nxt[4];
        cur[0] = *(const float4*)(xr0 + koff);
        cur[1] = *(const float4*)(xr1 + koff);
        cur[2] = *(const float4*)(xr2 + koff);
        cur[3] = *(const float4*)(xr3 + koff);
#pragma unroll 4
        for (int c = 0; c < 32; c++) {
            if (c < 31) {
                const int kn = koff + c * 4 + 4;
                nxt[0] = *(const float4*)(xr0 + kn);
                nxt[1] = *(const float4*)(xr1 + kn);
                nxt[2] = *(const float4*)(xr2 + kn);
                nxt[3] = *(const float4*)(xr3 + kn);
            }
#pragma unroll
            for (int j = 0; j < 4; j++) {
                const int kk = c * 4 + j;
                float4 b0 = *(const float4*)&sF[kk][tx * 8];
                float4 b1 = *(const float4*)&sF[kk][tx * 8 + 4];
                ull bb0 = *(ull*)&b0.x, bb1 = *(ull*)&b0.z;
                ull bb2 = *(ull*)&b1.x, bb3 = *(ull*)&b1.z;
#pragma unroll
                for (int r = 0; r < 4; r++) {
                    float av = ((const float*)&cur[r])[j];
                    ull ad; PACKDUP(ad, av);
                    FMA2(acc[r][0], ad, bb0, acc[r][0]);
                    FMA2(acc[r][1], ad, bb1, acc[r][1]);
                    FMA2(acc[r][2], ad, bb2, acc[r][2]);
                    FMA2(acc[r][3], ad, bb3, acc[r][3]);
                }
            }
#pragma unroll
            for (int r = 0; r < 4; r++) cur[r] = nxt[r];
        }
    }
    // store per-split partials (no atomics)
    float* base = &g_part[((size_t)blockIdx.y * ROWS + m0 + ty * 4) * KDIM + tx * 8];
#pragma unroll
    for (int r = 0; r < 4; r++) {
        float2 p0 = *(float2*)&acc[r][0];
        float2 p1 = *(float2*)&acc[r][1];
        float2 p2 = *(float2*)&acc[r][2];
        float2 p3 = *(float2*)&acc[r][3];
        *(float4*)(base + (size_t)r * KDIM)     = make_float4(p0.x, p0.y, p1.x, p1.y);
        *(float4*)(base + (size_t)r * KDIM + 4) = make_float4(p2.x, p2.y, p3.x, p3.y);
    }
}

// ---------------- reduce forward partials: g_sfor = sum over splits -------
__global__ void k_reduce() {
    int e = (blockIdx.x * 256 + threadIdx.x) * 4;
    if (e >= ROWS * KDIM) return;
    float4 s = make_float4(0.f, 0.f, 0.f, 0.f);
#pragma unroll 8
    for (int p = 0; p < KSPLIT; p++) {
        float4 v = *(const float4*)&g_part[(size_t)p * ROWS * KDIM + e];
        s.x += v.x; s.y += v.y; s.z += v.z; s.w += v.w;
    }
    *(float4*)&g_sfor[e] = s;
}

// ---------------- CFT magnitude + fused LayerNorm (256 thr, split dot) ----
__global__ void k_mag(const float* __restrict__ x,
                      const float* __restrict__ gamma,
                      const float* __restrict__ beta) {
    __shared__ float v[NNODES];
    __shared__ float pre[8][MODES], pim[8][MODES];
    const int row = blockIdx.x;
    const int tid = threadIdx.x;
    if (tid < NNODES) {
        int l = g_nodeL[tid];
        v[tid] = g_nodeWL[tid] * x[(size_t)row * NSAMP + l]
               + g_nodeWR[tid] * x[(size_t)row * NSAMP + l + 1];
    }
    __syncthreads();
    {
        const int w = tid >> 5, f = tid & 31;
        float re = 0.0f, im = 0.0f;
        const int j0 = w * 20;
#pragma unroll
        for (int j = 0; j < 20; j++) {
            float vv = v[j0 + j];
            re = fmaf(vv, __ldg(&g_Ar[(j0 + j) * MODES + f]), re);
            im = fmaf(vv, __ldg(&g_Ai[(j0 + j) * MODES + f]), im);
        }
        pre[w][f] = re; pim[w][f] = im;
    }
    __syncthreads();
    if (tid < MODES) {
        float re = 0.0f, im = 0.0f;
#pragma unroll
        for (int w = 0; w < 8; w++) { re += pre[w][tid]; im += pim[w][tid]; }
        float mag = sqrtf(re * re + im * im);
        float mu = mag;
#pragma unroll
        for (int s = 16; s > 0; s >>= 1) mu += __shfl_xor_sync(0xffffffffu, mu, s);
        mu *= (1.0f / MODES);
        float d = mag - mu;
        float var = d * d;
#pragma unroll
        for (int s = 16; s > 0; s >>= 1) var += __shfl_xor_sync(0xffffffffu, var, s);
        var *= (1.0f / MODES);
        float inv = rsqrtf(var + 1e-5f);
        g_norm[(size_t)row * MODES + tid] = d * inv * gamma[tid] + beta[tid];
    }
}

// ---------------- 1x1 conv gate (one block per batch b) -------------------
__global__ void k_gate(const float* __restrict__ gate_w) {
    __shared__ float sg[CH * MODES];
    const int b = blockIdx.x;
    const int tid = threadIdx.x;
    for (int e = tid; e < CH * MODES; e += blockDim.x)
        sg[e] = g_norm[(size_t)b * CH * MODES + e];
    __syncthreads();
    for (int e = tid; e < CH * MODES; e += blockDim.x) {
        int o = e >> 5, f = e & 31;
        float z = 0.0f;
#pragma unroll 8
        for (int i = 0; i < CH; i++)
            z = fmaf(__ldg(&gate_w[o * CH + i]), sg[i * MODES + f], z);
        g_gate[(size_t)b * CH * MODES + e] = 1.0f / (1.0f + expf(-z));
    }
}

// -------- per-(b,f) 64x64 complex matvec + irfft coefficient prep ---------
__global__ void k_modes() {
    const int b = blockIdx.x, f = blockIdx.y;
    const int o = threadIdx.x;
    __shared__ float gr[CH], gi[CH];
    {
        int i = o;
        float g = g_gate[((size_t)b * CH + i) * MODES + f];
        gr[i] =  g_sfor[((size_t)b * CH + i) * KDIM + f] * g;          // xr * gate
        gi[i] = -g_sfor[((size_t)b * CH + i) * KDIM + MODES + f] * g;  // xi * gate
    }
    __syncthreads();
    float orr = 0.0f, oii = 0.0f;
    const float* wr = &g_w1Tr[(size_t)f * CH * CH];
    const float* wi = &g_w1Ti[(size_t)f * CH * CH];
#pragma unroll 8
    for (int i = 0; i < CH; i++) {
        float a = gr[i], c = gi[i];
        float xr = wr[i * CH + o], xi = wi[i * CH + o];
        orr = fmaf(a, xr, orr); orr = fmaf(-c, xi, orr);
        oii = fmaf(a, xi, oii); oii = fmaf( c, xr, oii);
    }
    // irfft of 32-mode-truncated spectrum; imag of bin 0 ignored by hc2r
    float sc = (f == 0) ? (1.0f / NSAMP) : (2.0f / NSAMP);
    int row = b * CH + o;
    g_coef[(size_t)row * KDIM + f] = sc * orr;
    g_coef[(size_t)row * KDIM + MODES + f] = (f == 0) ? 0.0f : (-sc * oii);
}

// ---------------- inverse: out = coef[2048x64] * FtabT[64x8192] -----------
// grid (32, 32). block: 64 rows x 256 cols; 256 thr; tile 8 rows x 8 cols.
// coef tile dup'd in smem (broadcast LDS.128); FtabT streamed with prefetch.
__global__ __launch_bounds__(256) void k_inverse(float* __restrict__ out) {
    __shared__ float2 sctd[KDIM][64];     // [k][row] duplicated, 32KB
    const int n0 = blockIdx.x * 256;
    const int r0 = blockIdx.y * 64;
    const int tid = threadIdx.x;
    const int tx = tid & 31, ty = tid >> 5;   // cols tx*8.., rows ty*8..
    {
        int row = tid >> 2;
        int kq = (tid & 3) * 16;
#pragma unroll
        for (int q = 0; q < 4; q++) {
            float4 v = *(const float4*)&g_coef[(size_t)(r0 + row) * KDIM + kq + q * 4];
            sctd[kq + q * 4 + 0][row] = make_float2(v.x, v.x);
            sctd[kq + q * 4 + 1][row] = make_float2(v.y, v.y);
            sctd[kq + q * 4 + 2][row] = make_float2(v.z, v.z);
            sctd[kq + q * 4 + 3][row] = make_float2(v.w, v.w);
        }
    }
    __syncthreads();
    const float* bp = &g_FtabT[n0 + tx * 8];
    ull acc[8][4];
#pragma unroll
    for (int r = 0; r < 8; r++)
#pragma unroll
        for (int j = 0; j < 4; j++) acc[r][j] = 0ull;

    float4 c0 = *(const float4*)bp;
    float4 c1 = *(const float4*)(bp + 4);
#pragma unroll 4
    for (int k = 0; k < KDIM; k++) {
        float4 nf0, nf1;
        if (k < KDIM - 1) {
            nf0 = *(const float4*)(bp + (size_t)(k + 1) * NSAMP);
            nf1 = *(const float4*)(bp + (size_t)(k + 1) * NSAMP + 4);
        }
        ull b0 = *(ull*)&c0.x, b1 = *(ull*)&c0.z;
        ull b2 = *(ull*)&c1.x, b3 = *(ull*)&c1.z;
#pragma unroll
        for (int u = 0; u < 4; u++) {
            float4 aa = *(const float4*)&sctd[k][ty * 8 + u * 2];  // rows 2u,2u+1 dup
            ull a0 = *(ull*)&aa.x, a1 = *(ull*)&aa.z;
            FMA2(acc[2*u  ][0], a0, b0, acc[2*u  ][0]);
            FMA2(acc[2*u  ][1], a0, b1, acc[2*u  ][1]);
            FMA2(acc[2*u  ][2], a0, b2, acc[2*u  ][2]);
            FMA2(acc[2*u  ][3], a0, b3, acc[2*u  ][3]);
            FMA2(acc[2*u+1][0], a1, b0, acc[2*u+1][0]);
            FMA2(acc[2*u+1][1], a1, b1, acc[2*u+1][1]);
            FMA2(acc[2*u+1][2], a1, b2, acc[2*u+1][2]);
            FMA2(acc[2*u+1][3], a1, b3, acc[2*u+1][3]);
        }
        c0 = nf0; c1 = nf1;
    }
#pragma unroll
    for (int r = 0; r < 8; r++) {
        float2 p0 = *(float2*)&acc[r][0];
        float2 p1 = *(float2*)&acc[r][1];
        float2 p2 = *(float2*)&acc[r][2];
        float2 p3 = *(float2*)&acc[r][3];
        float* dst = &out[(size_t)(r0 + ty * 8 + r) * NSAMP + n0 + tx * 8];
        *(float4*)dst       = make_float4(p0.x, p0.y, p1.x, p1.y);
        *(float4*)(dst + 4) = make_float4(p2.x, p2.y, p3.x, p3.y);
    }
}

// ---------------- launch ----------------
extern "C" void kernel_launch(void* const* d_in, const int* in_sizes, int n_in,
                              void* d_out, int out_size) {
    const float* x     = (const float*)d_in[0];
    const float* w1r   = (const float*)d_in[1];
    const float* w1i   = (const float*)d_in[2];
    const float* gw    = (const float*)d_in[3];
    const float* gamma = (const float*)d_in[4];
    const float* beta  = (const float*)d_in[5];
    float* out = (float*)d_out;

    k_setup_F<<<(2 * NSAMP * KDIM + 255) / 256, 256>>>();
    k_setup_WA<<<1, 256>>>();
    k_transpose_w1<<<CH * CH / 32, 256>>>(w1r, w1i);
    k_forward<<<dim3(ROWS / 128, KSPLIT), 256>>>(x);
    k_reduce<<<ROWS * KDIM / 4 / 256, 256>>>();
    k_mag<<<ROWS, 256>>>(x, gamma, beta);
    k_gate<<<BATCH, 256>>>(gw);
    k_modes<<<dim3(BATCH, MODES), CH>>>();
    k_inverse<<<dim3(NSAMP / 256, ROWS / 64), 256>>>(out);
}

// round 10
// speedup vs baseline: 8.6808x; 1.3133x over previous
#include <cuda_runtime.h>
#include <cuda_bf16.h>
#include <mma.h>
#include <math.h>
#include <stdint.h>

using namespace nvcuda;

#define NSAMP 8192
#define MODES 32
#define KDIM  64          // 32 cos + 32 sin rows (freq-major)
#define BATCH 32
#define CH    64
#define ROWS  2048        // BATCH*CH
#define LSEG  20
#define MCHEB 8
#define NNODES 160        // LSEG*MCHEB
#define KSPLIT 16         // forward k-splits (512 k per CTA)
#define NSLICE KSPLIT
#define NCHUNK 16         // 512 / 32
#define BK     32
#define LDA    40         // padded lds (multiple of 8)
#define LDB    40

typedef unsigned long long ull;

// packed f32x2 FMA (sm_103a FFMA2; PTX-only) — used by the inverse
#define FMA2(d, a, b, c) \
    asm("fma.rn.f32x2 %0, %1, %2, %3;" : "=l"(d) : "l"(a), "l"(b), "l"(c))

// ---------------- device scratch (no allocations allowed) ----------------
__device__ float          g_FtabT[KDIM*NSAMP];     // [k][n] fp32 (inverse)
__device__ __nv_bfloat16  g_Fhi[KDIM*NSAMP];       // [freq][n] bf16 hi
__device__ __nv_bfloat16  g_Flo[KDIM*NSAMP];       // [freq][n] bf16 lo
__device__ float          g_part[NSLICE*ROWS*KDIM]; // forward partials (8MB)
__device__ float          g_Ar[NNODES*MODES];
__device__ float          g_Ai[NNODES*MODES];
__device__ int            g_nodeL[NNODES];
__device__ float          g_nodeWL[NNODES];
__device__ float          g_nodeWR[NNODES];
__device__ float          g_sfor[ROWS*KDIM];
__device__ float          g_norm[ROWS*MODES];
__device__ float          g_gate[BATCH*CH*MODES];
__device__ float          g_coef[ROWS*KDIM];
__device__ float          g_w1Tr[MODES*CH*CH];
__device__ float          g_w1Ti[MODES*CH*CH];

// ---------------- setup: DFT twiddle tables (fp32 + bf16 hi/lo) -----------
__global__ void k_setup_F() {
    int idx = blockIdx.x * blockDim.x + threadIdx.x;
    if (idx >= KDIM * NSAMP) return;
    int k = idx >> 13, n = idx & (NSAMP - 1);
    int kf = k & 31;
    int m = (n * kf) & (NSAMP - 1);                       // exact phase mod 2pi
    float xm = (float)m * (1.0f / 4096.0f);               // exact (pow2 denom)
    float v = (k < MODES) ? cospif(xm) : sinpif(xm);
    g_FtabT[idx] = v;
    __nv_bfloat16 hi = __float2bfloat16_rn(v);
    g_Fhi[idx] = hi;
    g_Flo[idx] = __float2bfloat16_rn(v - __bfloat162float(hi));
}

// ---------------- setup: CFT quadrature (one block, mostly float) ---------
__global__ void k_setup_WA() {
    __shared__ float sWr[MCHEB * MODES], sWi[MCHEB * MODES];
    const int tid = threadIdx.x;                          // 256 threads
    const float PIf = 3.14159265358979323846f;
    {
        int kc = tid >> 5, f = tid & 31;
        float Wr = 0.0f, Wi = 0.0f;
        for (int mp = 0; mp < MCHEB; mp++) {
            float chebp = -cosf((2.0f * mp + 1.0f) * PIf / (2.0f * MCHEB));
            float Tkm = cosf((float)kc * acosf(chebp));
            float ang = chebp * (float)f * (PIf / (float)LSEG);
            Wr += Tkm * cosf(ang);
            Wi += Tkm * (-sinf(ang));
        }
        float s = 1.0f / (2.0f * LSEG);
        sWr[tid] = Wr * s;
        sWi[tid] = Wi * s;
    }
    if (tid < NNODES) {
        int l = tid / MCHEB, m = tid % MCHEB;
        double cheb = -cos((2.0 * m + 1.0) * 3.14159265358979323846 / (2.0 * MCHEB));
        double tseg = (double)l / LSEG + (1.0 / (2.0 * LSEG)) * (cheb + 1.0);
        int right = (int)ceil(tseg * (double)(NSAMP - 1));
        if (right < 1) right = 1;
        if (right > NSAMP - 1) right = NSAMP - 1;
        int left = right - 1;
        double wr = tseg * (double)(NSAMP - 1) - (double)left;
        g_nodeL[tid]  = left;
        g_nodeWR[tid] = (float)wr;
        g_nodeWL[tid] = (float)(1.0 - wr);
    }
    __syncthreads();
    for (int idx = tid; idx < NNODES * MODES; idx += 256) {
        int j = idx >> 5, f = idx & 31;
        int l = j >> 3, mc = j & 7;
        float Wr = sWr[mc * MODES + f], Wi = sWi[mc * MODES + f];
        int r = (l * f) % LSEG;
        float ph = (float)r * (2.0f / (float)LSEG);
        float cphi = cospif(ph), sphi = sinpif(ph);
        g_Ar[idx] =  Wr * cphi + Wi * sphi;
        g_Ai[idx] = -Wr * sphi + Wi * cphi;
    }
}

// ---------------- setup: transpose w1 to f-major (tiled, coalesced) -------
__global__ void k_transpose_w1(const float* __restrict__ wr, const float* __restrict__ wi) {
    __shared__ float tr[32][33], ti[32][33];
    const int rbase = blockIdx.x * 32;
    const int t = threadIdx.x;            // 256
    {
        int f = t & 31, rr = t >> 5;
#pragma unroll
        for (int s = 0; s < 4; s++) {
            int r = rr + s * 8;
            tr[r][f] = __ldg(&wr[(size_t)(rbase + r) * MODES + f]);
            ti[r][f] = __ldg(&wi[(size_t)(rbase + r) * MODES + f]);
        }
    }
    __syncthreads();
    {
        int r = t & 31, ff = t >> 5;
#pragma unroll
        for (int s = 0; s < 4; s++) {
            int f = ff + s * 8;
            g_w1Tr[(size_t)f * (CH * CH) + rbase + r] = tr[r][f];
            g_w1Ti[(size_t)f * (CH * CH) + rbase + r] = ti[r][f];
        }
    }
}

// ---------------- forward GEMM via WMMA split-bf16 -----------------------
// grid (16 row-tiles, 16 k-splits). 256 threads = 8 warps.
// S += Xhi*(Fhi+Flo) + Xlo*Fhi,  fp32 accumulators.
__global__ __launch_bounds__(256) void k_forward_wmma(const float* __restrict__ x) {
    __shared__ __nv_bfloat16 sAhi[128][LDA];   // [row][k]
    __shared__ __nv_bfloat16 sAlo[128][LDA];
    __shared__ __nv_bfloat16 sBhi[KDIM][LDB];  // [freq][k] (col_major B)
    __shared__ __nv_bfloat16 sBlo[KDIM][LDB];
    const int tid = threadIdx.x, wid = tid >> 5;
    const int m0 = blockIdx.x * 128;
    const int kbase = blockIdx.y * (NSAMP / KSPLIT);   // 512-wide window

    wmma::fragment<wmma::accumulator, 16, 16, 16, float> acc[4];
#pragma unroll
    for (int c = 0; c < 4; c++) wmma::fill_fragment(acc[c], 0.0f);

    for (int ch = 0; ch < NCHUNK; ch++) {
        const int kc = kbase + ch * BK;
        __syncthreads();
        // ---- A: 128 rows x 32 k fp32 -> bf16 hi/lo ----
        {
            int row = tid >> 3, kq = (tid & 7) * 4;     // 32 rows per pass
#pragma unroll
            for (int p = 0; p < 4; p++) {
                int r = row + p * 32;
                float4 f4 = *(const float4*)&x[(size_t)(m0 + r) * NSAMP + kc + kq];
                float vs[4] = {f4.x, f4.y, f4.z, f4.w};
#pragma unroll
                for (int u = 0; u < 4; u++) {
                    __nv_bfloat16 hi = __float2bfloat16_rn(vs[u]);
                    sAhi[r][kq + u] = hi;
                    sAlo[r][kq + u] = __float2bfloat16_rn(vs[u] - __bfloat162float(hi));
                }
            }
        }
        // ---- B: 64 freq x 32 k bf16, straight copy ----
        {
            int f = tid >> 2, kq = (tid & 3) * 8;       // 256 thr cover 64x32/8
            *(uint4*)&sBhi[f][kq] = *(const uint4*)&g_Fhi[(size_t)f * NSAMP + kc + kq];
            *(uint4*)&sBlo[f][kq] = *(const uint4*)&g_Flo[(size_t)f * NSAMP + kc + kq];
        }
        __syncthreads();
#pragma unroll
        for (int ks = 0; ks < BK / 16; ks++) {
            wmma::fragment<wmma::matrix_a, 16, 16, 16, __nv_bfloat16, wmma::row_major> ahi, alo;
            wmma::load_matrix_sync(ahi, &sAhi[wid * 16][ks * 16], LDA);
            wmma::load_matrix_sync(alo, &sAlo[wid * 16][ks * 16], LDA);
#pragma unroll
            for (int c = 0; c < 4; c++) {
                wmma::fragment<wmma::matrix_b, 16, 16, 16, __nv_bfloat16, wmma::col_major> bhi, blo;
                wmma::load_matrix_sync(bhi, &sBhi[c * 16][ks * 16], LDB);
                wmma::load_matrix_sync(blo, &sBlo[c * 16][ks * 16], LDB);
                wmma::mma_sync(acc[c], ahi, bhi, acc[c]);
                wmma::mma_sync(acc[c], ahi, blo, acc[c]);
                wmma::mma_sync(acc[c], alo, bhi, acc[c]);
            }
        }
    }
    float* dst = &g_part[(size_t)blockIdx.y * ROWS * KDIM + (size_t)(m0 + wid * 16) * KDIM];
#pragma unroll
    for (int c = 0; c < 4; c++)
        wmma::store_matrix_sync(dst + c * 16, acc[c], KDIM, wmma::mem_row_major);
}

// ---------------- reduce forward partials: g_sfor = sum over slices -------
__global__ void k_reduce() {
    int e = (blockIdx.x * 256 + threadIdx.x) * 4;
    if (e >= ROWS * KDIM) return;
    float4 s = make_float4(0.f, 0.f, 0.f, 0.f);
#pragma unroll
    for (int p = 0; p < NSLICE; p++) {
        float4 v = *(const float4*)&g_part[(size_t)p * ROWS * KDIM + e];
        s.x += v.x; s.y += v.y; s.z += v.z; s.w += v.w;
    }
    *(float4*)&g_sfor[e] = s;
}

// ---------------- CFT magnitude + fused LayerNorm (256 thr, split dot) ----
__global__ void k_mag(const float* __restrict__ x,
                      const float* __restrict__ gamma,
                      const float* __restrict__ beta) {
    __shared__ float v[NNODES];
    __shared__ float pre[8][MODES], pim[8][MODES];
    const int row = blockIdx.x;
    const int tid = threadIdx.x;
    if (tid < NNODES) {
        int l = g_nodeL[tid];
        v[tid] = g_nodeWL[tid] * x[(size_t)row * NSAMP + l]
               + g_nodeWR[tid] * x[(size_t)row * NSAMP + l + 1];
    }
    __syncthreads();
    {
        const int w = tid >> 5, f = tid & 31;
        float re = 0.0f, im = 0.0f;
        const int j0 = w * 20;
#pragma unroll
        for (int j = 0; j < 20; j++) {
            float vv = v[j0 + j];
            re = fmaf(vv, __ldg(&g_Ar[(j0 + j) * MODES + f]), re);
            im = fmaf(vv, __ldg(&g_Ai[(j0 + j) * MODES + f]), im);
        }
        pre[w][f] = re; pim[w][f] = im;
    }
    __syncthreads();
    if (tid < MODES) {
        float re = 0.0f, im = 0.0f;
#pragma unroll
        for (int w = 0; w < 8; w++) { re += pre[w][tid]; im += pim[w][tid]; }
        float mag = sqrtf(re * re + im * im);
        float mu = mag;
#pragma unroll
        for (int s = 16; s > 0; s >>= 1) mu += __shfl_xor_sync(0xffffffffu, mu, s);
        mu *= (1.0f / MODES);
        float d = mag - mu;
        float var = d * d;
#pragma unroll
        for (int s = 16; s > 0; s >>= 1) var += __shfl_xor_sync(0xffffffffu, var, s);
        var *= (1.0f / MODES);
        float inv = rsqrtf(var + 1e-5f);
        g_norm[(size_t)row * MODES + tid] = d * inv * gamma[tid] + beta[tid];
    }
}

// ---------------- 1x1 conv gate (one block per batch b) -------------------
__global__ void k_gate(const float* __restrict__ gate_w) {
    __shared__ float sg[CH * MODES];
    const int b = blockIdx.x;
    const int tid = threadIdx.x;
    for (int e = tid; e < CH * MODES; e += blockDim.x)
        sg[e] = g_norm[(size_t)b * CH * MODES + e];
    __syncthreads();
    for (int e = tid; e < CH * MODES; e += blockDim.x) {
        int o = e >> 5, f = e & 31;
        float z = 0.0f;
#pragma unroll 8
        for (int i = 0; i < CH; i++)
            z = fmaf(__ldg(&gate_w[o * CH + i]), sg[i * MODES + f], z);
        g_gate[(size_t)b * CH * MODES + e] = 1.0f / (1.0f + expf(-z));
    }
}

// -------- per-(b,f) 64x64 complex matvec + irfft coefficient prep ---------
__global__ void k_modes() {
    const int b = blockIdx.x, f = blockIdx.y;
    const int o = threadIdx.x;
    __shared__ float gr[CH], gi[CH];
    {
        int i = o;
        float g = g_gate[((size_t)b * CH + i) * MODES + f];
        gr[i] =  g_sfor[((size_t)b * CH + i) * KDIM + f] * g;
        gi[i] = -g_sfor[((size_t)b * CH + i) * KDIM + MODES + f] * g;
    }
    __syncthreads();
    float orr = 0.0f, oii = 0.0f;
    const float* wr = &g_w1Tr[(size_t)f * CH * CH];
    const float* wi = &g_w1Ti[(size_t)f * CH * CH];
#pragma unroll 8
    for (int i = 0; i < CH; i++) {
        float a = gr[i], c = gi[i];
        float xr = wr[i * CH + o], xi = wi[i * CH + o];
        orr = fmaf(a, xr, orr); orr = fmaf(-c, xi, orr);
        oii = fmaf(a, xi, oii); oii = fmaf( c, xr, oii);
    }
    float sc = (f == 0) ? (1.0f / NSAMP) : (2.0f / NSAMP);
    int row = b * CH + o;
    g_coef[(size_t)row * KDIM + f] = sc * orr;
    g_coef[(size_t)row * KDIM + MODES + f] = (f == 0) ? 0.0f : (-sc * oii);
}

// ---------------- inverse: out = coef[2048x64] * FtabT[64x8192] -----------
__global__ __launch_bounds__(256) void k_inverse(float* __restrict__ out) {
    __shared__ float2 sctd[KDIM][64];     // [k][row] duplicated, 32KB
    const int n0 = blockIdx.x * 256;
    const int r0 = blockIdx.y * 64;
    const int tid = threadIdx.x;
    const int tx = tid & 31, ty = tid >> 5;
    {
        int row = tid >> 2;
        int kq = (tid & 3) * 16;
#pragma unroll
        for (int q = 0; q < 4; q++) {
            float4 v = *(const float4*)&g_coef[(size_t)(r0 + row) * KDIM + kq + q * 4];
            sctd[kq + q * 4 + 0][row] = make_float2(v.x, v.x);
            sctd[kq + q * 4 + 1][row] = make_float2(v.y, v.y);
            sctd[kq + q * 4 + 2][row] = make_float2(v.z, v.z);
            sctd[kq + q * 4 + 3][row] = make_float2(v.w, v.w);
        }
    }
    __syncthreads();
    const float* bp = &g_FtabT[n0 + tx * 8];
    ull acc[8][4];
#pragma unroll
    for (int r = 0; r < 8; r++)
#pragma unroll
        for (int j = 0; j < 4; j++) acc[r][j] = 0ull;

    float4 c0 = *(const float4*)bp;
    float4 c1 = *(const float4*)(bp + 4);
#pragma unroll 4
    for (int k = 0; k < KDIM; k++) {
        float4 nf0, nf1;
        if (k < KDIM - 1) {
            nf0 = *(const float4*)(bp + (size_t)(k + 1) * NSAMP);
            nf1 = *(const float4*)(bp + (size_t)(k + 1) * NSAMP + 4);
        }
        ull b0 = *(ull*)&c0.x, b1 = *(ull*)&c0.z;
        ull b2 = *(ull*)&c1.x, b3 = *(ull*)&c1.z;
#pragma unroll
        for (int u = 0; u < 4; u++) {
            float4 aa = *(const float4*)&sctd[k][ty * 8 + u * 2];
            ull a0 = *(ull*)&aa.x, a1 = *(ull*)&aa.z;
            FMA2(acc[2*u  ][0], a0, b0, acc[2*u  ][0]);
            FMA2(acc[2*u  ][1], a0, b1, acc[2*u  ][1]);
            FMA2(acc[2*u  ][2], a0, b2, acc[2*u  ][2]);
            FMA2(acc[2*u  ][3], a0, b3, acc[2*u  ][3]);
            FMA2(acc[2*u+1][0], a1, b0, acc[2*u+1][0]);
            FMA2(acc[2*u+1][1], a1, b1, acc[2*u+1][1]);
            FMA2(acc[2*u+1][2], a1, b2, acc[2*u+1][2]);
            FMA2(acc[2*u+1][3], a1, b3, acc[2*u+1][3]);
        }
        c0 = nf0; c1 = nf1;
    }
#pragma unroll
    for (int r = 0; r < 8; r++) {
        float2 p0 = *(float2*)&acc[r][0];
        float2 p1 = *(float2*)&acc[r][1];
        float2 p2 = *(float2*)&acc[r][2];
        float2 p3 = *(float2*)&acc[r][3];
        float* dst = &out[(size_t)(r0 + ty * 8 + r) * NSAMP + n0 + tx * 8];
        *(float4*)dst       = make_float4(p0.x, p0.y, p1.x, p1.y);
        *(float4*)(dst + 4) = make_float4(p2.x, p2.y, p3.x, p3.y);
    }
}

// ---------------- launch ----------------
extern "C" void kernel_launch(void* const* d_in, const int* in_sizes, int n_in,
                              void* d_out, int out_size) {
    const float* x     = (const float*)d_in[0];
    const float* w1r   = (const float*)d_in[1];
    const float* w1i   = (const float*)d_in[2];
    const float* gw    = (const float*)d_in[3];
    const float* gamma = (const float*)d_in[4];
    const float* beta  = (const float*)d_in[5];
    float* out = (float*)d_out;

    k_setup_F<<<KDIM * NSAMP / 256, 256>>>();
    k_setup_WA<<<1, 256>>>();
    k_transpose_w1<<<CH * CH / 32, 256>>>(w1r, w1i);
    k_forward_wmma<<<dim3(ROWS / 128, KSPLIT), 256>>>(x);
    k_reduce<<<ROWS * KDIM / 4 / 256, 256>>>();
    k_mag<<<ROWS, 256>>>(x, gamma, beta);
    k_gate<<<BATCH, 256>>>(gw);
    k_modes<<<dim3(BATCH, MODES), CH>>>();
    k_inverse<<<dim3(NSAMP / 256, ROWS / 64), 256>>>(out);
}

// round 11
// speedup vs baseline: 10.0080x; 1.1529x over previous
#include <cuda_runtime.h>
#include <cuda_bf16.h>
#include <mma.h>
#include <math.h>
#include <stdint.h>

using namespace nvcuda;

#define NSAMP 8192
#define MODES 32
#define KDIM  64          // 32 cos + 32 sin rows (freq-major)
#define BATCH 32
#define CH    64
#define ROWS  2048        // BATCH*CH
#define LSEG  20
#define MCHEB 8
#define NNODES 160        // LSEG*MCHEB
#define KSPLIT 16         // forward k-splits (512 k per CTA)
#define NSLICE KSPLIT
#define NCHUNK 16         // 512 / 32
#define BK     32
#define LDA    40         // padded lds (multiple of 8)
#define LDB    40
#define LDI    72         // inverse smem pad

typedef unsigned long long ull;

// ---------------- device scratch (no allocations allowed) ----------------
__device__ __nv_bfloat16  g_Fhi[KDIM*NSAMP];       // [freq][n] bf16 hi
__device__ __nv_bfloat16  g_Flo[KDIM*NSAMP];       // [freq][n] bf16 lo
__device__ float          g_part[NSLICE*ROWS*KDIM]; // forward partials (8MB)
__device__ float          g_Ar[NNODES*MODES];
__device__ float          g_Ai[NNODES*MODES];
__device__ int            g_nodeL[NNODES];
__device__ float          g_nodeWL[NNODES];
__device__ float          g_nodeWR[NNODES];
__device__ float          g_sfor[ROWS*KDIM];
__device__ float          g_norm[ROWS*MODES];
__device__ float          g_gate[BATCH*CH*MODES];
__device__ __nv_bfloat16  g_coefHi[ROWS*KDIM];     // irfft coefficients hi
__device__ __nv_bfloat16  g_coefLo[ROWS*KDIM];     // irfft coefficients lo
__device__ float          g_w1Tr[MODES*CH*CH];
__device__ float          g_w1Ti[MODES*CH*CH];

// ---------------- setup: DFT twiddle tables (bf16 hi/lo) ------------------
__global__ void k_setup_F() {
    int idx = blockIdx.x * blockDim.x + threadIdx.x;
    if (idx >= KDIM * NSAMP) return;
    int k = idx >> 13, n = idx & (NSAMP - 1);
    int kf = k & 31;
    int m = (n * kf) & (NSAMP - 1);                       // exact phase mod 2pi
    float xm = (float)m * (1.0f / 4096.0f);               // exact (pow2 denom)
    float v = (k < MODES) ? cospif(xm) : sinpif(xm);
    __nv_bfloat16 hi = __float2bfloat16_rn(v);
    g_Fhi[idx] = hi;
    g_Flo[idx] = __float2bfloat16_rn(v - __bfloat162float(hi));
}

// ---------------- setup: CFT quadrature (one block, mostly float) ---------
__global__ void k_setup_WA() {
    __shared__ float sWr[MCHEB * MODES], sWi[MCHEB * MODES];
    const int tid = threadIdx.x;                          // 256 threads
    const float PIf = 3.14159265358979323846f;
    {
        int kc = tid >> 5, f = tid & 31;
        float Wr = 0.0f, Wi = 0.0f;
        for (int mp = 0; mp < MCHEB; mp++) {
            float chebp = -cosf((2.0f * mp + 1.0f) * PIf / (2.0f * MCHEB));
            float Tkm = cosf((float)kc * acosf(chebp));
            float ang = chebp * (float)f * (PIf / (float)LSEG);
            Wr += Tkm * cosf(ang);
            Wi += Tkm * (-sinf(ang));
        }
        float s = 1.0f / (2.0f * LSEG);
        sWr[tid] = Wr * s;
        sWi[tid] = Wi * s;
    }
    if (tid < NNODES) {
        int l = tid / MCHEB, m = tid % MCHEB;
        double cheb = -cos((2.0 * m + 1.0) * 3.14159265358979323846 / (2.0 * MCHEB));
        double tseg = (double)l / LSEG + (1.0 / (2.0 * LSEG)) * (cheb + 1.0);
        int right = (int)ceil(tseg * (double)(NSAMP - 1));
        if (right < 1) right = 1;
        if (right > NSAMP - 1) right = NSAMP - 1;
        int left = right - 1;
        double wr = tseg * (double)(NSAMP - 1) - (double)left;
        g_nodeL[tid]  = left;
        g_nodeWR[tid] = (float)wr;
        g_nodeWL[tid] = (float)(1.0 - wr);
    }
    __syncthreads();
    for (int idx = tid; idx < NNODES * MODES; idx += 256) {
        int j = idx >> 5, f = idx & 31;
        int l = j >> 3, mc = j & 7;
        float Wr = sWr[mc * MODES + f], Wi = sWi[mc * MODES + f];
        int r = (l * f) % LSEG;
        float ph = (float)r * (2.0f / (float)LSEG);
        float cphi = cospif(ph), sphi = sinpif(ph);
        g_Ar[idx] =  Wr * cphi + Wi * sphi;
        g_Ai[idx] = -Wr * sphi + Wi * cphi;
    }
}

// ---------------- setup: transpose w1 to f-major (tiled, coalesced) -------
__global__ void k_transpose_w1(const float* __restrict__ wr, const float* __restrict__ wi) {
    __shared__ float tr[32][33], ti[32][33];
    const int rbase = blockIdx.x * 32;
    const int t = threadIdx.x;            // 256
    {
        int f = t & 31, rr = t >> 5;
#pragma unroll
        for (int s = 0; s < 4; s++) {
            int r = rr + s * 8;
            tr[r][f] = __ldg(&wr[(size_t)(rbase + r) * MODES + f]);
            ti[r][f] = __ldg(&wi[(size_t)(rbase + r) * MODES + f]);
        }
    }
    __syncthreads();
    {
        int r = t & 31, ff = t >> 5;
#pragma unroll
        for (int s = 0; s < 4; s++) {
            int f = ff + s * 8;
            g_w1Tr[(size_t)f * (CH * CH) + rbase + r] = tr[r][f];
            g_w1Ti[(size_t)f * (CH * CH) + rbase + r] = ti[r][f];
        }
    }
}

// ---------------- forward GEMM via WMMA split-bf16 -----------------------
// grid (16 row-tiles, 16 k-splits). 256 threads = 8 warps.
// S += Xhi*(Fhi+Flo) + Xlo*Fhi,  fp32 accumulators.
__global__ __launch_bounds__(256) void k_forward_wmma(const float* __restrict__ x) {
    __shared__ __align__(32) __nv_bfloat16 sAhi[128][LDA];   // [row][k]
    __shared__ __align__(32) __nv_bfloat16 sAlo[128][LDA];
    __shared__ __align__(32) __nv_bfloat16 sBhi[KDIM][LDB];  // [freq][k]
    __shared__ __align__(32) __nv_bfloat16 sBlo[KDIM][LDB];
    const int tid = threadIdx.x, wid = tid >> 5;
    const int m0 = blockIdx.x * 128;
    const int kbase = blockIdx.y * (NSAMP / KSPLIT);   // 512-wide window

    wmma::fragment<wmma::accumulator, 16, 16, 16, float> acc[4];
#pragma unroll
    for (int c = 0; c < 4; c++) wmma::fill_fragment(acc[c], 0.0f);

    for (int ch = 0; ch < NCHUNK; ch++) {
        const int kc = kbase + ch * BK;
        __syncthreads();
        // ---- A: 128 rows x 32 k fp32 -> bf16 hi/lo (packed converts) ----
        {
            int row = tid >> 3, kq = (tid & 7) * 4;
#pragma unroll
            for (int p = 0; p < 4; p++) {
                int r = row + p * 32;
                float4 f4 = *(const float4*)&x[(size_t)(m0 + r) * NSAMP + kc + kq];
                uint32_t h01, h23, l01, l23;
                asm("cvt.rn.bf16x2.f32 %0, %1, %2;" : "=r"(h01) : "f"(f4.y), "f"(f4.x));
                asm("cvt.rn.bf16x2.f32 %0, %1, %2;" : "=r"(h23) : "f"(f4.w), "f"(f4.z));
                float hx = __uint_as_float(h01 << 16);
                float hy = __uint_as_float(h01 & 0xFFFF0000u);
                float hz = __uint_as_float(h23 << 16);
                float hw = __uint_as_float(h23 & 0xFFFF0000u);
                asm("cvt.rn.bf16x2.f32 %0, %1, %2;" : "=r"(l01) : "f"(f4.y - hy), "f"(f4.x - hx));
                asm("cvt.rn.bf16x2.f32 %0, %1, %2;" : "=r"(l23) : "f"(f4.w - hw), "f"(f4.z - hz));
                *(uint2*)&sAhi[r][kq] = make_uint2(h01, h23);
                *(uint2*)&sAlo[r][kq] = make_uint2(l01, l23);
            }
        }
        // ---- B: 64 freq x 32 k bf16, straight copy ----
        {
            int f = tid >> 2, kq = (tid & 3) * 8;
            *(uint4*)&sBhi[f][kq] = *(const uint4*)&g_Fhi[(size_t)f * NSAMP + kc + kq];
            *(uint4*)&sBlo[f][kq] = *(const uint4*)&g_Flo[(size_t)f * NSAMP + kc + kq];
        }
        __syncthreads();
#pragma unroll
        for (int ks = 0; ks < BK / 16; ks++) {
            wmma::fragment<wmma::matrix_a, 16, 16, 16, __nv_bfloat16, wmma::row_major> ahi, alo;
            wmma::load_matrix_sync(ahi, &sAhi[wid * 16][ks * 16], LDA);
            wmma::load_matrix_sync(alo, &sAlo[wid * 16][ks * 16], LDA);
#pragma unroll
            for (int c = 0; c < 4; c++) {
                wmma::fragment<wmma::matrix_b, 16, 16, 16, __nv_bfloat16, wmma::col_major> bhi, blo;
                wmma::load_matrix_sync(bhi, &sBhi[c * 16][ks * 16], LDB);
                wmma::load_matrix_sync(blo, &sBlo[c * 16][ks * 16], LDB);
                wmma::mma_sync(acc[c], ahi, bhi, acc[c]);
                wmma::mma_sync(acc[c], ahi, blo, acc[c]);
                wmma::mma_sync(acc[c], alo, bhi, acc[c]);
            }
        }
    }
    float* dst = &g_part[(size_t)blockIdx.y * ROWS * KDIM + (size_t)(m0 + wid * 16) * KDIM];
#pragma unroll
    for (int c = 0; c < 4; c++)
        wmma::store_matrix_sync(dst + c * 16, acc[c], KDIM, wmma::mem_row_major);
}

// ---------------- reduce forward partials: g_sfor = sum over slices -------
__global__ void k_reduce() {
    int e = (blockIdx.x * 256 + threadIdx.x) * 4;
    if (e >= ROWS * KDIM) return;
    float4 s = make_float4(0.f, 0.f, 0.f, 0.f);
#pragma unroll
    for (int p = 0; p < NSLICE; p++) {
        float4 v = *(const float4*)&g_part[(size_t)p * ROWS * KDIM + e];
        s.x += v.x; s.y += v.y; s.z += v.z; s.w += v.w;
    }
    *(float4*)&g_sfor[e] = s;
}

// ---------------- CFT magnitude + fused LayerNorm (256 thr, split dot) ----
__global__ void k_mag(const float* __restrict__ x,
                      const float* __restrict__ gamma,
                      const float* __restrict__ beta) {
    __shared__ float v[NNODES];
    __shared__ float pre[8][MODES], pim[8][MODES];
    const int row = blockIdx.x;
    const int tid = threadIdx.x;
    if (tid < NNODES) {
        int l = g_nodeL[tid];
        v[tid] = g_nodeWL[tid] * x[(size_t)row * NSAMP + l]
               + g_nodeWR[tid] * x[(size_t)row * NSAMP + l + 1];
    }
    __syncthreads();
    {
        const int w = tid >> 5, f = tid & 31;
        float re = 0.0f, im = 0.0f;
        const int j0 = w * 20;
#pragma unroll
        for (int j = 0; j < 20; j++) {
            float vv = v[j0 + j];
            re = fmaf(vv, __ldg(&g_Ar[(j0 + j) * MODES + f]), re);
            im = fmaf(vv, __ldg(&g_Ai[(j0 + j) * MODES + f]), im);
        }
        pre[w][f] = re; pim[w][f] = im;
    }
    __syncthreads();
    if (tid < MODES) {
        float re = 0.0f, im = 0.0f;
#pragma unroll
        for (int w = 0; w < 8; w++) { re += pre[w][tid]; im += pim[w][tid]; }
        float mag = sqrtf(re * re + im * im);
        float mu = mag;
#pragma unroll
        for (int s = 16; s > 0; s >>= 1) mu += __shfl_xor_sync(0xffffffffu, mu, s);
        mu *= (1.0f / MODES);
        float d = mag - mu;
        float var = d * d;
#pragma unroll
        for (int s = 16; s > 0; s >>= 1) var += __shfl_xor_sync(0xffffffffu, var, s);
        var *= (1.0f / MODES);
        float inv = rsqrtf(var + 1e-5f);
        g_norm[(size_t)row * MODES + tid] = d * inv * gamma[tid] + beta[tid];
    }
}

// ---------------- 1x1 conv gate (one block per batch b) -------------------
__global__ void k_gate(const float* __restrict__ gate_w) {
    __shared__ float sg[CH * MODES];
    const int b = blockIdx.x;
    const int tid = threadIdx.x;
    for (int e = tid; e < CH * MODES; e += blockDim.x)
        sg[e] = g_norm[(size_t)b * CH * MODES + e];
    __syncthreads();
    for (int e = tid; e < CH * MODES; e += blockDim.x) {
        int o = e >> 5, f = e & 31;
        float z = 0.0f;
#pragma unroll 8
        for (int i = 0; i < CH; i++)
            z = fmaf(__ldg(&gate_w[o * CH + i]), sg[i * MODES + f], z);
        g_gate[(size_t)b * CH * MODES + e] = 1.0f / (1.0f + expf(-z));
    }
}

// -------- per-(b,f) 64x64 complex matvec; coef written as bf16 hi/lo ------
__global__ void k_modes() {
    const int b = blockIdx.x, f = blockIdx.y;
    const int o = threadIdx.x;
    __shared__ float gr[CH], gi[CH];
    {
        int i = o;
        float g = g_gate[((size_t)b * CH + i) * MODES + f];
        gr[i] =  g_sfor[((size_t)b * CH + i) * KDIM + f] * g;
        gi[i] = -g_sfor[((size_t)b * CH + i) * KDIM + MODES + f] * g;
    }
    __syncthreads();
    float orr = 0.0f, oii = 0.0f;
    const float* wr = &g_w1Tr[(size_t)f * CH * CH];
    const float* wi = &g_w1Ti[(size_t)f * CH * CH];
#pragma unroll 8
    for (int i = 0; i < CH; i++) {
        float a = gr[i], c = gi[i];
        float xr = wr[i * CH + o], xi = wi[i * CH + o];
        orr = fmaf(a, xr, orr); orr = fmaf(-c, xi, orr);
        oii = fmaf(a, xi, oii); oii = fmaf( c, xr, oii);
    }
    float sc = (f == 0) ? (1.0f / NSAMP) : (2.0f / NSAMP);
    int row = b * CH + o;
    float cr = sc * orr;
    float ci = (f == 0) ? 0.0f : (-sc * oii);   // imag of bin 0 ignored by hc2r
    __nv_bfloat16 h;
    h = __float2bfloat16_rn(cr);
    g_coefHi[(size_t)row * KDIM + f] = h;
    g_coefLo[(size_t)row * KDIM + f] = __float2bfloat16_rn(cr - __bfloat162float(h));
    h = __float2bfloat16_rn(ci);
    g_coefHi[(size_t)row * KDIM + MODES + f] = h;
    g_coefLo[(size_t)row * KDIM + MODES + f] = __float2bfloat16_rn(ci - __bfloat162float(h));
}

// ---------------- inverse via WMMA split-bf16 -----------------------------
// out[2048x8192] = coef[2048x64] * F[64x8192].  grid (128, 32), 64x64 tiles.
// out += Chi*(Fhi+Flo) + Clo*Fhi.
__global__ __launch_bounds__(256) void k_inverse_wmma(float* __restrict__ out) {
    __shared__ __align__(32) __nv_bfloat16 sA[2][64][LDI];  // [hi/lo][row][k]
    __shared__ __align__(32) __nv_bfloat16 sB[2][64][LDI];  // [hi/lo][freq][n]
    const int tid = threadIdx.x, w = tid >> 5;
    const int n0 = blockIdx.x * 64;
    const int r0 = blockIdx.y * 64;
    {
        int r = tid >> 2, c = (tid & 3) * 16;
        *(uint4*)&sA[0][r][c]     = *(const uint4*)&g_coefHi[(size_t)(r0 + r) * KDIM + c];
        *(uint4*)&sA[0][r][c + 8] = *(const uint4*)&g_coefHi[(size_t)(r0 + r) * KDIM + c + 8];
        *(uint4*)&sA[1][r][c]     = *(const uint4*)&g_coefLo[(size_t)(r0 + r) * KDIM + c];
        *(uint4*)&sA[1][r][c + 8] = *(const uint4*)&g_coefLo[(size_t)(r0 + r) * KDIM + c + 8];
        *(uint4*)&sB[0][r][c]     = *(const uint4*)&g_Fhi[(size_t)r * NSAMP + n0 + c];
        *(uint4*)&sB[0][r][c + 8] = *(const uint4*)&g_Fhi[(size_t)r * NSAMP + n0 + c + 8];
        *(uint4*)&sB[1][r][c]     = *(const uint4*)&g_Flo[(size_t)r * NSAMP + n0 + c];
        *(uint4*)&sB[1][r][c + 8] = *(const uint4*)&g_Flo[(size_t)r * NSAMP + n0 + c + 8];
    }
    __syncthreads();
    const int wm = w & 3, wn = w >> 2;
    wmma::fragment<wmma::accumulator, 16, 16, 16, float> acc[2];
#pragma unroll
    for (int t = 0; t < 2; t++) wmma::fill_fragment(acc[t], 0.0f);
#pragma unroll
    for (int kt = 0; kt < 4; kt++) {
        wmma::fragment<wmma::matrix_a, 16, 16, 16, __nv_bfloat16, wmma::row_major> ahi, alo;
        wmma::load_matrix_sync(ahi, &sA[0][wm * 16][kt * 16], LDI);
        wmma::load_matrix_sync(alo, &sA[1][wm * 16][kt * 16], LDI);
#pragma unroll
        for (int nt = 0; nt < 2; nt++) {
            int nc = (wn * 2 + nt) * 16;
            wmma::fragment<wmma::matrix_b, 16, 16, 16, __nv_bfloat16, wmma::row_major> bhi, blo;
            wmma::load_matrix_sync(bhi, &sB[0][kt * 16][nc], LDI);
            wmma::load_matrix_sync(blo, &sB[1][kt * 16][nc], LDI);
            wmma::mma_sync(acc[nt], ahi, bhi, acc[nt]);
            wmma::mma_sync(acc[nt], ahi, blo, acc[nt]);
            wmma::mma_sync(acc[nt], alo, bhi, acc[nt]);
        }
    }
#pragma unroll
    for (int nt = 0; nt < 2; nt++)
        wmma::store_matrix_sync(&out[(size_t)(r0 + wm * 16) * NSAMP + n0 + (wn * 2 + nt) * 16],
                                acc[nt], NSAMP, wmma::mem_row_major);
}

// ---------------- launch ----------------
extern "C" void kernel_launch(void* const* d_in, const int* in_sizes, int n_in,
                              void* d_out, int out_size) {
    const float* x     = (const float*)d_in[0];
    const float* w1r   = (const float*)d_in[1];
    const float* w1i   = (const float*)d_in[2];
    const float* gw    = (const float*)d_in[3];
    const float* gamma = (const float*)d_in[4];
    const float* beta  = (const float*)d_in[5];
    float* out = (float*)d_out;

    k_setup_F<<<KDIM * NSAMP / 256, 256>>>();
    k_setup_WA<<<1, 256>>>();
    k_transpose_w1<<<CH * CH / 32, 256>>>(w1r, w1i);
    k_forward_wmma<<<dim3(ROWS / 128, KSPLIT), 256>>>(x);
    k_reduce<<<ROWS * KDIM / 4 / 256, 256>>>();
    k_mag<<<ROWS, 256>>>(x, gamma, beta);
    k_gate<<<BATCH, 256>>>(gw);
    k_modes<<<dim3(BATCH, MODES), CH>>>();
    k_inverse_wmma<<<dim3(NSAMP / 64, ROWS / 64), 256>>>(out);
}